// round 7
// baseline (speedup 1.0000x reference)
#include <cuda_runtime.h>
#include <math.h>

#define N_ANCH 21840
#define NWORDS 342            // ceil(21840/64) tiles
#define NSTATE 683            // ceil(21840/32), 2 bits per rank
#define NBLK   86             // ceil(21840/256) for k_final
#define NDIG   4096           // 12-bit high digit
#define CAP    192            // max higher-rank suppressors per box
#define NB     148            // persistent grid = #SMs (1 block/SM, co-resident)
#define BT     512
#define NWARP  (NB * (BT / 32))
#define NMS_THF 0.3f
#define FIN_THF 0.5f
#define FULLM 0xFFFFFFFFu

// ---- static device scratch (zero at module load; recycled state reset by k_final) ----
__device__ float g_x1[N_ANCH], g_y1[N_ANCH], g_x2[N_ANCH], g_y2[N_ANCH];
__device__ float g_sc[N_ANCH], g_area[N_ANCH];
__device__ unsigned g_key[N_ANCH];
__device__ int g_hist[NDIG];            // re-zeroed by k_final
__device__ int g_base[NDIG], g_cursor[NDIG];
__device__ unsigned g_bin[N_ANCH];      // (low12 << 15) | idx
__device__ int g_srank[N_ANCH];
__device__ int g_kcnt;
__device__ float g_tminx1[NWORDS], g_tminy1[NWORDS], g_tmaxx2[NWORDS], g_tmaxy2[NWORDS];
__device__ float g_tamin[NWORDS], g_tamax[NWORDS];
__device__ unsigned short g_nbr[(size_t)N_ANCH * CAP];  // by rank
__device__ int g_ncnt[N_ANCH];                           // by rank
__device__ unsigned long long g_state[NSTATE];
__device__ unsigned g_barc[8];          // grid-barrier counters, reset by k_final

struct InPtrs { const float* cls[6]; const float* reg[6]; };

// software grid barrier: all NB blocks co-resident (1/SM); counters monotone per launch
__device__ __forceinline__ void gbar(int phase) {
    __syncthreads();
    if (threadIdx.x == 0) {
        __threadfence();
        atomicAdd(&g_barc[phase], 1u);
        while (atomicAdd(&g_barc[phase], 0u) < (unsigned)NB) __nanosleep(64);
        __threadfence();
    }
    __syncthreads();
}

__global__ void __launch_bounds__(BT) k_main(InPtrs in) {
    __shared__ float m0[BT], m1[BT], m2[BT], m3[BT], m4[BT], m5[BT];
    __shared__ int wsum[16];
    __shared__ unsigned long long state[NSTATE];
    __shared__ int more;

    int t = threadIdx.x;
    int bid = blockIdx.x;
    int lane = t & 31, wid = t >> 5;

    // ================= phase 0: decode (bit-exact) + key + hist + tile bboxes =================
    {
        int i = bid * BT + t;
        bool on = i < N_ANCH;
        float x1 = 0.f, y1 = 0.f, x2 = 0.f, y2 = 0.f, prob = 0.f, area = 0.f;
        if (on) {
            const int offs[7]   = {0, 16384, 20480, 21504, 21760, 21824, 21840};
            const int maps[6]   = {128, 64, 32, 16, 8, 4};
            const float strd[6] = {4.f, 8.f, 16.f, 32.f, 64.f, 128.f};
            int sc = 0;
            #pragma unroll
            for (int k = 0; k < 5; k++) if (i >= offs[k + 1]) sc = k + 1;
            int local = i - offs[sc];
            int W = maps[sc];
            int y = local / W, x = local - y * W;
            int HW = W * W;
            const float* cls = in.cls[sc];
            const float* reg = in.reg[sc];

            float c0 = cls[local], c1 = cls[HW + local];
            float m  = fmaxf(c0, c1);
            float e0 = expf(__fsub_rn(c0, m));
            float e1 = expf(__fsub_rn(c1, m));
            prob = __fdiv_rn(e1, __fadd_rn(e0, e1));

            float s   = strd[sc];
            float pwh = s * 4.0f;
            float pcx = __fadd_rn(0.5f * s, __fmul_rn((float)x, s));
            float pcy = __fadd_rn(0.5f * s, __fmul_rn((float)y, s));
            float l0 = reg[local], l1 = reg[HW + local];
            float l2 = reg[2 * HW + local], l3 = reg[3 * HW + local];
            float cx = __fadd_rn(pcx, __fmul_rn(__fmul_rn(l0, 0.1f), pwh));
            float cy = __fadd_rn(pcy, __fmul_rn(__fmul_rn(l1, 0.1f), pwh));
            float w  = __fmul_rn(pwh, expf(__fmul_rn(l2, 0.2f)));
            float h  = __fmul_rn(pwh, expf(__fmul_rn(l3, 0.2f)));
            x1 = __fsub_rn(cx, __fmul_rn(w, 0.5f));
            y1 = __fsub_rn(cy, __fmul_rn(h, 0.5f));
            x2 = __fadd_rn(x1, w);
            y2 = __fadd_rn(y1, h);
            area = __fmul_rn(__fadd_rn(__fsub_rn(x2, x1), 1.0f),
                             __fadd_rn(__fsub_rn(y2, y1), 1.0f));

            g_x1[i] = x1; g_y1[i] = y1; g_x2[i] = x2; g_y2[i] = y2;
            g_sc[i] = prob; g_area[i] = area;

            unsigned u   = __float_as_uint(prob);
            unsigned k24 = (~(u | 0x80000000u)) - 0x407FFFFFu;
            bool valid = prob > FIN_THF;
            g_key[i] = valid ? k24 : 0xFFFFFFFFu;
            if (valid) atomicAdd(&g_hist[k24 >> 12], 1);
        }

        bool v = on && (prob > FIN_THF);
        m0[t] = v ? x1 :  1e30f;
        m1[t] = v ? y1 :  1e30f;
        m2[t] = v ? x2 : -1e30f;
        m3[t] = v ? y2 : -1e30f;
        m4[t] = v ? area :  1e30f;
        m5[t] = v ? area : -1e30f;
        int o = t & 63;
        for (int s = 32; s > 0; s >>= 1) {
            __syncthreads();
            if (o < s) {
                m0[t] = fminf(m0[t], m0[t + s]);
                m1[t] = fminf(m1[t], m1[t + s]);
                m2[t] = fmaxf(m2[t], m2[t + s]);
                m3[t] = fmaxf(m3[t], m3[t + s]);
                m4[t] = fminf(m4[t], m4[t + s]);
                m5[t] = fmaxf(m5[t], m5[t + s]);
            }
        }
        if (o == 0) {
            int tile = bid * 8 + (t >> 6);
            if (tile < NWORDS) {
                g_tminx1[tile] = m0[t]; g_tminy1[tile] = m1[t];
                g_tmaxx2[tile] = m2[t]; g_tmaxy2[tile] = m3[t];
                g_tamin[tile]  = m4[t]; g_tamax[tile]  = m5[t];
            }
        }
    }
    gbar(0);

    // ================= phase 1: exclusive scan of 4096 digit counts (block 0) =================
    if (bid == 0) {
        int loc[8], pre[8];
        int s = 0;
        #pragma unroll
        for (int q = 0; q < 8; q++) { loc[q] = g_hist[t * 8 + q]; pre[q] = s; s += loc[q]; }
        int x = s;
        #pragma unroll
        for (int k = 1; k < 32; k <<= 1) { int y = __shfl_up_sync(FULLM, x, k); if (lane >= k) x += y; }
        if (lane == 31) wsum[wid] = x;
        __syncthreads();
        if (wid == 0 && lane < 16) {
            int wv = wsum[lane];
            #pragma unroll
            for (int k = 1; k < 16; k <<= 1) { int y = __shfl_up_sync(0xFFFFu, wv, k); if (lane >= k) wv += y; }
            wsum[lane] = wv;
        }
        __syncthreads();
        int base = x - s + ((wid > 0) ? wsum[wid - 1] : 0);
        #pragma unroll
        for (int q = 0; q < 8; q++) {
            int b = base + pre[q];
            g_base[t * 8 + q] = b;
            g_cursor[t * 8 + q] = b;
        }
        if (t == BT - 1) g_kcnt = base + s;   // total valid
    }
    gbar(1);

    // ================= phase 2: unstable scatter into bins =================
    {
        int i = bid * BT + t;
        if (i < N_ANCH) {
            unsigned k = g_key[i];
            if (k != 0xFFFFFFFFu) {
                int d = k >> 12;
                int pos = atomicAdd(&g_cursor[d], 1);
                g_bin[pos] = ((k & 0xFFFu) << 15) | (unsigned)i;   // unique composite
            }
        }
    }
    gbar(2);

    // ================= phase 3: in-bin ranking (warp per bin) =================
    {
        int gw = bid * (BT / 32) + wid;
        for (int d = gw; d < NDIG - 1; d += NWARP) {
            int base = g_base[d];
            int n = __ldcg(&g_cursor[d]) - base;   // L2 read: atomics updated L2 behind block0's L1
            if (n == 0) continue;
            if (n <= 32) {
                unsigned rec = (lane < n) ? g_bin[base + lane] : 0xFFFFFFFFu;
                int r = 0;
                for (int k = 0; k < n; k++) {
                    unsigned other = __shfl_sync(FULLM, rec, k);
                    r += (other < rec) ? 1 : 0;
                }
                if (lane < n) g_srank[rec & 0x7FFFu] = base + r;
            } else {
                for (int e = lane; e < n; e += 32) {
                    unsigned rec = g_bin[base + e];
                    int r = 0;
                    for (int k = 0; k < n; k++) r += (g_bin[base + k] < rec) ? 1 : 0;
                    g_srank[rec & 0x7FFFu] = base + r;
                }
            }
        }
    }
    gbar(3);

    // ================= phase 4: sparse suppressor lists (warp per box) =================
    {
        int gw = bid * (BT / 32) + wid;
        for (int i = gw; i < N_ANCH; i += NWARP) {
            if (!(g_sc[i] > FIN_THF)) continue;   // uniform per warp
            float x1 = g_x1[i], y1 = g_y1[i], x2 = g_x2[i], y2 = g_y2[i], ai = g_area[i];
            int ri = g_srank[i];
            int cnt = 0;
            for (int tb = 0; tb < NWORDS; tb += 32) {
                int tt0 = tb + lane;
                bool act = false;
                if (tt0 < NWORDS) {
                    float bw = __fadd_rn(__fsub_rn(fminf(x2, g_tmaxx2[tt0]), fmaxf(x1, g_tminx1[tt0])), 1.0f);
                    float bh = __fadd_rn(__fsub_rn(fminf(y2, g_tmaxy2[tt0]), fmaxf(y1, g_tminy1[tt0])), 1.0f);
                    float lo = fminf(ai, g_tamax[tt0]);
                    float hi = fmaxf(ai, g_tamin[tt0]);
                    act = (bw > 0.f) && (bh > 0.f) && (lo > 0.299f * hi);  // conservative
                }
                unsigned bal = __ballot_sync(FULLM, act);
                while (bal) {
                    int tt = __ffs(bal) - 1;
                    bal &= bal - 1;
                    int j0 = (tb + tt) << 6;
                    #pragma unroll
                    for (int h = 0; h < 2; h++) {
                        int j = j0 + h * 32 + lane;
                        bool hit = false;
                        int rj = 0;
                        if (j < N_ANCH) {
                            rj = g_srank[j];
                            if ((g_sc[j] > FIN_THF) && rj < ri) {
                                float xx1 = fmaxf(x1, g_x1[j]);
                                float yy1 = fmaxf(y1, g_y1[j]);
                                float xx2 = fminf(x2, g_x2[j]);
                                float yy2 = fminf(y2, g_y2[j]);
                                float w  = fmaxf(__fadd_rn(__fsub_rn(xx2, xx1), 1.f), 0.f);
                                float hh = fmaxf(__fadd_rn(__fsub_rn(yy2, yy1), 1.f), 0.f);
                                float inter = __fmul_rn(w, hh);
                                float aj = g_area[j];
                                if (inter > 0.299f * fmaxf(ai, aj)) {
                                    float iou = __fdiv_rn(inter, __fsub_rn(__fadd_rn(ai, aj), inter));
                                    hit = iou > NMS_THF;
                                }
                            }
                        }
                        unsigned hb = __ballot_sync(FULLM, hit);
                        if (hit) {
                            int off = cnt + __popc(hb & ((1u << lane) - 1));
                            if (off < CAP) g_nbr[(size_t)ri * CAP + off] = (unsigned short)rj;
                        }
                        cnt += __popc(hb);
                    }
                }
            }
            if (lane == 0) g_ncnt[ri] = min(cnt, CAP);
        }
    }
    gbar(4);

    // ================= phase 5: rank-ordered fixed-point resolve (block 0) =================
    if (bid == 0) {
        int kcnt = g_kcnt;
        for (int w = t; w < NSTATE; w += BT) {
            int base = w << 5;
            unsigned long long sw = 0;
            for (int b = 0; b < 32; b++)
                if (base + b >= kcnt) sw |= 1ull << (2 * b);
            state[w] = sw;
        }
        if (t == 0) more = 0;
        __syncthreads();

        int chunk = (kcnt + BT - 1) / BT;
        int lo = t * chunk, hi = min(lo + chunk, kcnt);
        bool mydone = (lo >= hi);
        for (;;) {
            int lm = 0;
            if (!mydone) {
                bool alldone = true;
                for (int r = lo; r < hi; r++) {
                    unsigned long long sv = state[r >> 5] >> ((r & 31) * 2);
                    if (sv & 1ull) continue;
                    int cn = g_ncnt[r];
                    const unsigned short* lst = g_nbr + (size_t)r * CAP;
                    bool anyk = false, allres = true;
                    for (int e = 0; e < cn; e++) {
                        int c = lst[e];
                        unsigned long long cs = state[c >> 5] >> ((c & 31) * 2);
                        if (cs & 2ull) { anyk = true; break; }
                        if (!(cs & 1ull)) allres = false;
                    }
                    if (anyk)
                        atomicOr(&state[r >> 5], 1ull << ((r & 31) * 2));
                    else if (allres)
                        atomicOr(&state[r >> 5], 3ull << ((r & 31) * 2));
                    else { lm = 1; alldone = false; }
                }
                mydone = alldone;
            }
            if (lm) more = 1;
            __syncthreads();
            int m = more;
            __syncthreads();
            if (!m) break;
            if (t == 0) more = 0;
            __syncthreads();
        }
        for (int w = t; w < NSTATE; w += BT) g_state[w] = state[w];
    }
}

// ---------------- K2: final masked write + state reset for next replay ----------------
__global__ void k_final(float* __restrict__ out) {
    int i = blockIdx.x * blockDim.x + threadIdx.x;
    if (i < NDIG) g_hist[i] = 0;
    if (i < 8) g_barc[i] = 0;
    if (i >= N_ANCH) return;
    float sc = g_sc[i];
    bool valid = sc > FIN_THF;
    int ri = valid ? g_srank[i] : 0;
    unsigned long long sv = g_state[ri >> 5] >> ((ri & 31) * 2);
    bool kp = valid && ((sv & 2ull) != 0ull);
    float f = kp ? 1.0f : 0.0f;
    out[i * 5 + 0] = __fmul_rn(g_x1[i], f);
    out[i * 5 + 1] = __fmul_rn(g_y1[i], f);
    out[i * 5 + 2] = __fmul_rn(g_x2[i], f);
    out[i * 5 + 3] = __fmul_rn(g_y2[i], f);
    out[i * 5 + 4] = __fmul_rn(sc, f);
}

extern "C" void kernel_launch(void* const* d_in, const int* in_sizes, int n_in,
                              void* d_out, int out_size) {
    (void)in_sizes; (void)n_in; (void)out_size;
    InPtrs p;
    for (int i = 0; i < 6; i++) {
        p.cls[i] = (const float*)d_in[2 * i];
        p.reg[i] = (const float*)d_in[2 * i + 1];
    }
    k_main<<<NB, BT>>>(p);
    k_final<<<NBLK, 256>>>((float*)d_out);
}

// round 8
// speedup vs baseline: 1.4735x; 1.4735x over previous
#include <cuda_runtime.h>
#include <math.h>

#define N_ANCH 21840
#define NWORDS 342            // ceil(21840/64) tiles
#define NSTATE 683            // ceil(21840/32), 2 bits per rank
#define NBLK   86             // ceil(21840/256)
#define NDIG   2048           // 11-bit high digit (valid keys only reach 0x7FF)
#define CAP    192            // max higher-rank suppressors per box
#define NMS_THF 0.3f
#define FIN_THF 0.5f
#define FULLM 0xFFFFFFFFu
#define RINV  0x7FFFFFFF      // rank sentinel for invalid boxes

// ---- static device scratch (zero at module load; g_hist re-zeroed by k_final) ----
__device__ float4 g_box[N_ANCH];        // x1,y1,x2,y2
__device__ float2 g_ra[N_ANCH];         // (area, rank-as-int-bits; RINV if invalid)
__device__ float g_sc[N_ANCH];
__device__ unsigned g_key[N_ANCH];
__device__ int g_hist[NDIG];
__device__ int g_base[NDIG], g_cursor[NDIG];
__device__ unsigned g_bin[N_ANCH];      // (low12 << 15) | idx
__device__ int g_kcnt;
__device__ float g_tminx1[NWORDS], g_tminy1[NWORDS], g_tmaxx2[NWORDS], g_tmaxy2[NWORDS];
__device__ float g_tamin[NWORDS], g_tamax[NWORDS];
__device__ unsigned short g_nbr[(size_t)N_ANCH * CAP];  // by rank
__device__ int g_ncnt[N_ANCH];                           // by rank
__device__ unsigned long long g_state[NSTATE];

struct InPtrs { const float* cls[6]; const float* reg[6]; };

// ---------------- K1: decode (bit-exact) + key + hist + tile bboxes ----------------
__global__ void k_decode(InPtrs in) {
    __shared__ float m0[256], m1[256], m2[256], m3[256], m4[256], m5[256];
    int t = threadIdx.x;
    int i = blockIdx.x * 256 + t;
    bool on = i < N_ANCH;

    float x1 = 0.f, y1 = 0.f, x2 = 0.f, y2 = 0.f, prob = 0.f, area = 0.f;
    if (on) {
        const int offs[7]   = {0, 16384, 20480, 21504, 21760, 21824, 21840};
        const int maps[6]   = {128, 64, 32, 16, 8, 4};
        const float strd[6] = {4.f, 8.f, 16.f, 32.f, 64.f, 128.f};
        int sc = 0;
        #pragma unroll
        for (int k = 0; k < 5; k++) if (i >= offs[k + 1]) sc = k + 1;
        int local = i - offs[sc];
        int W = maps[sc];
        int y = local / W, x = local - y * W;
        int HW = W * W;
        const float* cls = in.cls[sc];
        const float* reg = in.reg[sc];

        float c0 = cls[local], c1 = cls[HW + local];
        float m  = fmaxf(c0, c1);
        float e0 = expf(__fsub_rn(c0, m));
        float e1 = expf(__fsub_rn(c1, m));
        prob = __fdiv_rn(e1, __fadd_rn(e0, e1));

        float s   = strd[sc];
        float pwh = s * 4.0f;
        float pcx = __fadd_rn(0.5f * s, __fmul_rn((float)x, s));
        float pcy = __fadd_rn(0.5f * s, __fmul_rn((float)y, s));
        float l0 = reg[local], l1 = reg[HW + local];
        float l2 = reg[2 * HW + local], l3 = reg[3 * HW + local];
        float cx = __fadd_rn(pcx, __fmul_rn(__fmul_rn(l0, 0.1f), pwh));
        float cy = __fadd_rn(pcy, __fmul_rn(__fmul_rn(l1, 0.1f), pwh));
        float w  = __fmul_rn(pwh, expf(__fmul_rn(l2, 0.2f)));
        float h  = __fmul_rn(pwh, expf(__fmul_rn(l3, 0.2f)));
        x1 = __fsub_rn(cx, __fmul_rn(w, 0.5f));
        y1 = __fsub_rn(cy, __fmul_rn(h, 0.5f));
        x2 = __fadd_rn(x1, w);
        y2 = __fadd_rn(y1, h);
        area = __fmul_rn(__fadd_rn(__fsub_rn(x2, x1), 1.0f),
                         __fadd_rn(__fsub_rn(y2, y1), 1.0f));

        g_box[i] = make_float4(x1, y1, x2, y2);
        g_ra[i]  = make_float2(area, __int_as_float(RINV));
        g_sc[i]  = prob;

        unsigned u   = __float_as_uint(prob);
        unsigned k24 = (~(u | 0x80000000u)) - 0x407FFFFFu;   // valid -> [0,0x7FFFFF]
        bool valid = prob > FIN_THF;
        g_key[i] = valid ? k24 : 0xFFFFFFFFu;
        if (valid) atomicAdd(&g_hist[k24 >> 12], 1);
    }

    // fused per-64 tile bboxes (valid boxes only)
    bool v = on && (prob > FIN_THF);
    m0[t] = v ? x1 :  1e30f;
    m1[t] = v ? y1 :  1e30f;
    m2[t] = v ? x2 : -1e30f;
    m3[t] = v ? y2 : -1e30f;
    m4[t] = v ? area :  1e30f;
    m5[t] = v ? area : -1e30f;
    int o = t & 63;
    for (int s = 32; s > 0; s >>= 1) {
        __syncthreads();
        if (o < s) {
            m0[t] = fminf(m0[t], m0[t + s]);
            m1[t] = fminf(m1[t], m1[t + s]);
            m2[t] = fmaxf(m2[t], m2[t + s]);
            m3[t] = fmaxf(m3[t], m3[t + s]);
            m4[t] = fminf(m4[t], m4[t + s]);
            m5[t] = fmaxf(m5[t], m5[t + s]);
        }
    }
    if (o == 0) {
        int tile = blockIdx.x * 4 + (t >> 6);
        if (tile < NWORDS) {
            g_tminx1[tile] = m0[t]; g_tminy1[tile] = m1[t];
            g_tmaxx2[tile] = m2[t]; g_tmaxy2[tile] = m3[t];
            g_tamin[tile]  = m4[t]; g_tamax[tile]  = m5[t];
        }
    }
}

// ---------------- K2: exclusive scan of 2048 digit counts ----------------
__global__ void __launch_bounds__(1024) k_scan() {
    __shared__ int wsum[32];
    int t = threadIdx.x, lane = t & 31, wid = t >> 5;
    int a0 = g_hist[2 * t], a1 = g_hist[2 * t + 1];
    int s = a0 + a1;
    int x = s;
    #pragma unroll
    for (int k = 1; k < 32; k <<= 1) { int y = __shfl_up_sync(FULLM, x, k); if (lane >= k) x += y; }
    if (lane == 31) wsum[wid] = x;
    __syncthreads();
    if (wid == 0) {
        int wv = wsum[lane];
        #pragma unroll
        for (int k = 1; k < 32; k <<= 1) { int y = __shfl_up_sync(FULLM, wv, k); if (lane >= k) wv += y; }
        wsum[lane] = wv;
    }
    __syncthreads();
    int base = x - s + ((wid > 0) ? wsum[wid - 1] : 0);
    g_base[2 * t] = base;         g_cursor[2 * t] = base;
    g_base[2 * t + 1] = base + a0; g_cursor[2 * t + 1] = base + a0;
    if (t == 1023) g_kcnt = base + s;   // total valid
}

// ---------------- K3: unstable scatter into bins ----------------
__global__ void k_scatter() {
    int i = blockIdx.x * 256 + threadIdx.x;
    if (i >= N_ANCH) return;
    unsigned k = g_key[i];
    if (k == 0xFFFFFFFFu) return;
    int d = k >> 12;
    int pos = atomicAdd(&g_cursor[d], 1);
    g_bin[pos] = ((k & 0xFFFu) << 15) | (unsigned)i;   // unique composite, encodes stable order
}

// ---------------- K4: in-bin ranking (warp per bin) ----------------
__global__ void k_binsort() {
    int wid = threadIdx.x >> 5, lane = threadIdx.x & 31;
    int d = blockIdx.x * 8 + wid;
    if (d >= NDIG) return;
    int base = g_base[d];
    int n = g_cursor[d] - base;
    if (n == 0) return;
    int* rap = (int*)g_ra;
    if (n <= 32) {
        unsigned rec = (lane < n) ? g_bin[base + lane] : 0xFFFFFFFFu;
        int r = 0;
        for (int k = 0; k < n; k++) {
            unsigned other = __shfl_sync(FULLM, rec, k);
            r += (other < rec) ? 1 : 0;
        }
        if (lane < n) rap[2 * (rec & 0x7FFFu) + 1] = base + r;
    } else {
        for (int e = lane; e < n; e += 32) {
            unsigned rec = g_bin[base + e];
            int r = 0;
            for (int k = 0; k < n; k++) r += (g_bin[base + k] < rec) ? 1 : 0;
            rap[2 * (rec & 0x7FFFu) + 1] = base + r;
        }
    }
}

// ---------------- K5: sparse suppressor lists (warp per box) ----------------
__global__ void k_nbr() {
    __shared__ float sx1[NWORDS], sy1[NWORDS], sx2[NWORDS], sy2[NWORDS];
    __shared__ float sam[NWORDS], sax[NWORDS];
    int t = threadIdx.x, lane = t & 31, wid = t >> 5;
    for (int q = t; q < NWORDS; q += 256) {
        sx1[q] = g_tminx1[q]; sy1[q] = g_tminy1[q];
        sx2[q] = g_tmaxx2[q]; sy2[q] = g_tmaxy2[q];
        sam[q] = g_tamin[q];  sax[q] = g_tamax[q];
    }
    __syncthreads();
    int i = blockIdx.x * 8 + wid;
    if (i >= N_ANCH) return;
    float2 rai = g_ra[i];
    int ri = __float_as_int(rai.y);
    if (ri == RINV) return;   // invalid box (uniform per warp)
    float ai = rai.x;
    float4 bb = g_box[i];
    float x1 = bb.x, y1 = bb.y, x2 = bb.z, y2 = bb.w;
    int cnt = 0;
    for (int tb = 0; tb < NWORDS; tb += 32) {
        int tt0 = tb + lane;
        bool act = false;
        if (tt0 < NWORDS) {
            float bw = __fadd_rn(__fsub_rn(fminf(x2, sx2[tt0]), fmaxf(x1, sx1[tt0])), 1.0f);
            float bh = __fadd_rn(__fsub_rn(fminf(y2, sy2[tt0]), fmaxf(y1, sy1[tt0])), 1.0f);
            float lo = fminf(ai, sax[tt0]);
            float hi = fmaxf(ai, sam[tt0]);
            act = (bw > 0.f) && (bh > 0.f) && (lo > 0.299f * hi);  // conservative
        }
        unsigned bal = __ballot_sync(FULLM, act);
        while (bal) {
            int tt = __ffs(bal) - 1;
            bal &= bal - 1;
            int j0 = (tb + tt) << 6;
            #pragma unroll
            for (int h = 0; h < 2; h++) {
                int j = j0 + h * 32 + lane;
                bool hit = false;
                int rj = RINV;
                if (j < N_ANCH) {
                    float2 raj = g_ra[j];
                    rj = __float_as_int(raj.y);
                    if (rj < ri) {   // valid suppressor candidate (invalid j has RINV)
                        float4 bj = g_box[j];
                        float xx1 = fmaxf(x1, bj.x);
                        float yy1 = fmaxf(y1, bj.y);
                        float xx2 = fminf(x2, bj.z);
                        float yy2 = fminf(y2, bj.w);
                        float w  = fmaxf(__fadd_rn(__fsub_rn(xx2, xx1), 1.f), 0.f);
                        float hh = fmaxf(__fadd_rn(__fsub_rn(yy2, yy1), 1.f), 0.f);
                        float inter = __fmul_rn(w, hh);
                        float aj = raj.x;
                        if (inter > 0.299f * fmaxf(ai, aj)) {
                            float iou = __fdiv_rn(inter, __fsub_rn(__fadd_rn(ai, aj), inter));
                            hit = iou > NMS_THF;
                        }
                    }
                }
                unsigned hb = __ballot_sync(FULLM, hit);
                if (hit) {
                    int off = cnt + __popc(hb & ((1u << lane) - 1));
                    if (off < CAP) g_nbr[(size_t)ri * CAP + off] = (unsigned short)rj;
                }
                cnt += __popc(hb);
            }
        }
    }
    if (lane == 0) g_ncnt[ri] = min(cnt, CAP);
}

// ---------------- K6: rank-ordered fixed-point NMS resolve ----------------
// 2 bits per rank: bit0 = resolved, bit1 = kept
__global__ void __launch_bounds__(1024) k_resolve() {
    __shared__ unsigned long long state[NSTATE];
    __shared__ int more;
    int t = threadIdx.x;
    int kcnt = g_kcnt;
    for (int w = t; w < NSTATE; w += 1024) {
        int base = w << 5;
        unsigned long long sw = 0;
        for (int b = 0; b < 32; b++)
            if (base + b >= kcnt) sw |= 1ull << (2 * b);   // rank >= kcnt: resolved, not kept
        state[w] = sw;
    }
    if (t == 0) more = 0;
    __syncthreads();

    int chunk = (kcnt + 1023) >> 10;
    int lo = t * chunk, hi = min(lo + chunk, kcnt);
    bool mydone = (lo >= hi);
    for (;;) {
        int lm = 0;
        if (!mydone) {
            bool alldone = true;
            for (int r = lo; r < hi; r++) {
                unsigned long long sv = state[r >> 5] >> ((r & 31) * 2);
                if (sv & 1ull) continue;
                int cn = g_ncnt[r];
                const unsigned short* lst = g_nbr + (size_t)r * CAP;
                bool anyk = false, allres = true;
                for (int e = 0; e < cn; e++) {
                    int c = lst[e];
                    unsigned long long cs = state[c >> 5] >> ((c & 31) * 2);
                    if (cs & 2ull) { anyk = true; break; }
                    if (!(cs & 1ull)) allres = false;
                }
                if (anyk)
                    atomicOr(&state[r >> 5], 1ull << ((r & 31) * 2));
                else if (allres)
                    atomicOr(&state[r >> 5], 3ull << ((r & 31) * 2));
                else { lm = 1; alldone = false; }
            }
            mydone = alldone;
        }
        if (lm) more = 1;
        __syncthreads();
        int m = more;
        __syncthreads();
        if (!m) break;
        if (t == 0) more = 0;
        __syncthreads();
    }
    for (int w = t; w < NSTATE; w += 1024) g_state[w] = state[w];
}

// ---------------- K7: final masked write + hist re-zero for next replay ----------------
__global__ void k_final(float* __restrict__ out) {
    int i = blockIdx.x * blockDim.x + threadIdx.x;
    if (i < NDIG) g_hist[i] = 0;
    if (i >= N_ANCH) return;
    float sc = g_sc[i];
    int ri = __float_as_int(g_ra[i].y);
    bool kp = false;
    if (ri != RINV) {
        unsigned long long sv = g_state[ri >> 5] >> ((ri & 31) * 2);
        kp = (sv & 2ull) != 0ull;
    }
    float f = kp ? 1.0f : 0.0f;
    float4 bb = g_box[i];
    out[i * 5 + 0] = __fmul_rn(bb.x, f);
    out[i * 5 + 1] = __fmul_rn(bb.y, f);
    out[i * 5 + 2] = __fmul_rn(bb.z, f);
    out[i * 5 + 3] = __fmul_rn(bb.w, f);
    out[i * 5 + 4] = __fmul_rn(sc, f);
}

extern "C" void kernel_launch(void* const* d_in, const int* in_sizes, int n_in,
                              void* d_out, int out_size) {
    (void)in_sizes; (void)n_in; (void)out_size;
    InPtrs p;
    for (int i = 0; i < 6; i++) {
        p.cls[i] = (const float*)d_in[2 * i];
        p.reg[i] = (const float*)d_in[2 * i + 1];
    }
    k_decode<<<NBLK, 256>>>(p);
    k_scan<<<1, 1024>>>();
    k_scatter<<<NBLK, 256>>>();
    k_binsort<<<NDIG / 8, 256>>>();
    k_nbr<<<(N_ANCH + 7) / 8, 256>>>();
    k_resolve<<<1, 1024>>>();
    k_final<<<NBLK, 256>>>((float*)d_out);
}

// round 9
// speedup vs baseline: 2.0907x; 1.4189x over previous
#include <cuda_runtime.h>
#include <math.h>

#define N_ANCH 21840
#define NWORDS 342            // ceil(21840/64) tiles
#define NSTATE 683            // ceil(21840/32), 2 bits per rank
#define NBLK   86             // ceil(21840/256)
#define NDIG   2048           // 11-bit digit space (valid keys only reach 0x7FF)
#define CAP    192            // max higher-rank suppressors per box
#define NMS_THF 0.3f
#define FIN_THF 0.5f
#define FULLM 0xFFFFFFFFu
#define RINV  0x7FFFFFFF      // rank sentinel for invalid boxes

// ---- static device scratch (zero at module load; g_hist re-zeroed by k_final) ----
__device__ float g_x1[N_ANCH], g_y1[N_ANCH], g_x2[N_ANCH], g_y2[N_ANCH];
__device__ float g_sc[N_ANCH], g_area[N_ANCH];
__device__ unsigned g_key[N_ANCH];
__device__ int g_hist[NDIG];            // re-zeroed by k_final each replay
__device__ int g_base[NDIG], g_cursor[NDIG];
__device__ unsigned g_bin[N_ANCH];      // (low12 << 15) | idx
__device__ int g_srank[N_ANCH];         // RINV for invalid boxes
__device__ int g_kcnt;
__device__ float g_tminx1[NWORDS], g_tminy1[NWORDS], g_tmaxx2[NWORDS], g_tmaxy2[NWORDS];
__device__ float g_tamin[NWORDS], g_tamax[NWORDS];
__device__ unsigned short g_nbr[(size_t)N_ANCH * CAP];  // by rank
__device__ int g_ncnt[N_ANCH];                           // by rank
__device__ unsigned long long g_state[NSTATE];

struct InPtrs { const float* cls[6]; const float* reg[6]; };

// ---------------- K1: decode (bit-exact) + key + hist + tile bboxes ----------------
__global__ void k_decode(InPtrs in) {
    __shared__ float m0[256], m1[256], m2[256], m3[256], m4[256], m5[256];
    int t = threadIdx.x;
    int i = blockIdx.x * 256 + t;
    bool on = i < N_ANCH;

    float x1 = 0.f, y1 = 0.f, x2 = 0.f, y2 = 0.f, prob = 0.f, area = 0.f;
    if (on) {
        const int offs[7]   = {0, 16384, 20480, 21504, 21760, 21824, 21840};
        const int maps[6]   = {128, 64, 32, 16, 8, 4};
        const float strd[6] = {4.f, 8.f, 16.f, 32.f, 64.f, 128.f};
        int sc = 0;
        #pragma unroll
        for (int k = 0; k < 5; k++) if (i >= offs[k + 1]) sc = k + 1;
        int local = i - offs[sc];
        int W = maps[sc];
        int y = local / W, x = local - y * W;
        int HW = W * W;
        const float* cls = in.cls[sc];
        const float* reg = in.reg[sc];

        float c0 = cls[local], c1 = cls[HW + local];
        float m  = fmaxf(c0, c1);
        float e0 = expf(__fsub_rn(c0, m));
        float e1 = expf(__fsub_rn(c1, m));
        prob = __fdiv_rn(e1, __fadd_rn(e0, e1));

        float s   = strd[sc];
        float pwh = s * 4.0f;
        float pcx = __fadd_rn(0.5f * s, __fmul_rn((float)x, s));
        float pcy = __fadd_rn(0.5f * s, __fmul_rn((float)y, s));
        float l0 = reg[local], l1 = reg[HW + local];
        float l2 = reg[2 * HW + local], l3 = reg[3 * HW + local];
        float cx = __fadd_rn(pcx, __fmul_rn(__fmul_rn(l0, 0.1f), pwh));
        float cy = __fadd_rn(pcy, __fmul_rn(__fmul_rn(l1, 0.1f), pwh));
        float w  = __fmul_rn(pwh, expf(__fmul_rn(l2, 0.2f)));
        float h  = __fmul_rn(pwh, expf(__fmul_rn(l3, 0.2f)));
        x1 = __fsub_rn(cx, __fmul_rn(w, 0.5f));
        y1 = __fsub_rn(cy, __fmul_rn(h, 0.5f));
        x2 = __fadd_rn(x1, w);
        y2 = __fadd_rn(y1, h);
        area = __fmul_rn(__fadd_rn(__fsub_rn(x2, x1), 1.0f),
                         __fadd_rn(__fsub_rn(y2, y1), 1.0f));

        g_x1[i] = x1; g_y1[i] = y1; g_x2[i] = x2; g_y2[i] = y2;
        g_sc[i] = prob; g_area[i] = area;
        g_srank[i] = RINV;   // binsort overwrites for valid boxes

        // 24-bit key: prob in (0.5,1] -> [0, 0x7FFFFF]; ascending == descending score
        unsigned u   = __float_as_uint(prob);
        unsigned k24 = (~(u | 0x80000000u)) - 0x407FFFFFu;
        bool valid = prob > FIN_THF;
        g_key[i] = valid ? k24 : 0xFFFFFFFFu;
        if (valid) atomicAdd(&g_hist[k24 >> 12], 1);
    }

    // fused per-64 tile bboxes (valid boxes only)
    bool v = on && (prob > FIN_THF);
    m0[t] = v ? x1 :  1e30f;
    m1[t] = v ? y1 :  1e30f;
    m2[t] = v ? x2 : -1e30f;
    m3[t] = v ? y2 : -1e30f;
    m4[t] = v ? area :  1e30f;
    m5[t] = v ? area : -1e30f;
    int o = t & 63;
    for (int s = 32; s > 0; s >>= 1) {
        __syncthreads();
        if (o < s) {
            m0[t] = fminf(m0[t], m0[t + s]);
            m1[t] = fminf(m1[t], m1[t + s]);
            m2[t] = fmaxf(m2[t], m2[t + s]);
            m3[t] = fmaxf(m3[t], m3[t + s]);
            m4[t] = fminf(m4[t], m4[t + s]);
            m5[t] = fmaxf(m5[t], m5[t + s]);
        }
    }
    if (o == 0) {
        int tile = blockIdx.x * 4 + (t >> 6);
        if (tile < NWORDS) {
            g_tminx1[tile] = m0[t]; g_tminy1[tile] = m1[t];
            g_tmaxx2[tile] = m2[t]; g_tmaxy2[tile] = m3[t];
            g_tamin[tile]  = m4[t]; g_tamax[tile]  = m5[t];
        }
    }
}

// ---------------- K2: exclusive scan of 2048 digit counts ----------------
__global__ void __launch_bounds__(1024) k_scan() {
    __shared__ int wsum[32];
    int t = threadIdx.x, lane = t & 31, wid = t >> 5;
    int a0 = g_hist[2 * t], a1 = g_hist[2 * t + 1];
    int s = a0 + a1;
    int x = s;
    #pragma unroll
    for (int k = 1; k < 32; k <<= 1) { int y = __shfl_up_sync(FULLM, x, k); if (lane >= k) x += y; }
    if (lane == 31) wsum[wid] = x;
    __syncthreads();
    if (wid == 0) {
        int wv = wsum[lane];
        #pragma unroll
        for (int k = 1; k < 32; k <<= 1) { int y = __shfl_up_sync(FULLM, wv, k); if (lane >= k) wv += y; }
        wsum[lane] = wv;
    }
    __syncthreads();
    int base = x - s + ((wid > 0) ? wsum[wid - 1] : 0);
    g_base[2 * t] = base;          g_cursor[2 * t] = base;
    g_base[2 * t + 1] = base + a0; g_cursor[2 * t + 1] = base + a0;
    if (t == 1023) g_kcnt = base + s;   // total valid
}

// ---------------- K3: unstable scatter into bins ----------------
__global__ void k_scatter() {
    int i = blockIdx.x * 256 + threadIdx.x;
    if (i >= N_ANCH) return;
    unsigned k = g_key[i];
    if (k == 0xFFFFFFFFu) return;
    int d = k >> 12;
    int pos = atomicAdd(&g_cursor[d], 1);
    g_bin[pos] = ((k & 0xFFFu) << 15) | (unsigned)i;   // unique composite, stable order
}

// ---------------- K4: in-bin ranking (warp per bin) ----------------
__global__ void k_binsort() {
    int wid = threadIdx.x >> 5, lane = threadIdx.x & 31;
    int d = blockIdx.x * 8 + wid;
    if (d >= NDIG) return;
    int base = g_base[d];
    int n = g_cursor[d] - base;
    if (n == 0) return;
    if (n <= 32) {
        unsigned rec = (lane < n) ? g_bin[base + lane] : 0xFFFFFFFFu;
        int r = 0;
        for (int k = 0; k < n; k++) {
            unsigned other = __shfl_sync(FULLM, rec, k);
            r += (other < rec) ? 1 : 0;
        }
        if (lane < n) g_srank[rec & 0x7FFFu] = base + r;
    } else {
        for (int e = lane; e < n; e += 32) {
            unsigned rec = g_bin[base + e];
            int r = 0;
            for (int k = 0; k < n; k++) r += (g_bin[base + k] < rec) ? 1 : 0;
            g_srank[rec & 0x7FFFu] = base + r;
        }
    }
}

// ---------------- K5: sparse suppressor lists (warp per box, rank-indexed) ----------------
__global__ void k_nbr() {
    int i = (blockIdx.x * blockDim.x + threadIdx.x) >> 5;
    int lane = threadIdx.x & 31;
    if (i >= N_ANCH) return;
    int ri = g_srank[i];
    if (ri == RINV) return;   // invalid box (uniform per warp)
    float x1 = g_x1[i], y1 = g_y1[i], x2 = g_x2[i], y2 = g_y2[i], ai = g_area[i];
    int cnt = 0;
    for (int tb = 0; tb < NWORDS; tb += 32) {
        int t = tb + lane;
        bool act = false;
        if (t < NWORDS) {
            float bw = __fadd_rn(__fsub_rn(fminf(x2, g_tmaxx2[t]), fmaxf(x1, g_tminx1[t])), 1.0f);
            float bh = __fadd_rn(__fsub_rn(fminf(y2, g_tmaxy2[t]), fmaxf(y1, g_tminy1[t])), 1.0f);
            float lo = fminf(ai, g_tamax[t]);
            float hi = fmaxf(ai, g_tamin[t]);
            act = (bw > 0.f) && (bh > 0.f) && (lo > 0.299f * hi);  // conservative
        }
        unsigned bal = __ballot_sync(FULLM, act);
        while (bal) {
            int tt = __ffs(bal) - 1;
            bal &= bal - 1;
            int j0 = (tb + tt) << 6;
            #pragma unroll
            for (int h = 0; h < 2; h++) {
                int j = j0 + h * 32 + lane;
                bool hit = false;
                int rj = RINV;
                if (j < N_ANCH) {
                    rj = g_srank[j];
                    if (rj < ri) {   // sufficient: invalid j has rj == RINV
                        float xx1 = fmaxf(x1, g_x1[j]);
                        float yy1 = fmaxf(y1, g_y1[j]);
                        float xx2 = fminf(x2, g_x2[j]);
                        float yy2 = fminf(y2, g_y2[j]);
                        float w  = fmaxf(__fadd_rn(__fsub_rn(xx2, xx1), 1.f), 0.f);
                        float hh = fmaxf(__fadd_rn(__fsub_rn(yy2, yy1), 1.f), 0.f);
                        float inter = __fmul_rn(w, hh);
                        float aj = g_area[j];
                        if (inter > 0.299f * fmaxf(ai, aj)) {
                            float iou = __fdiv_rn(inter, __fsub_rn(__fadd_rn(ai, aj), inter));
                            hit = iou > NMS_THF;
                        }
                    }
                }
                unsigned hb = __ballot_sync(FULLM, hit);
                if (hit) {
                    int off = cnt + __popc(hb & ((1u << lane) - 1));
                    if (off < CAP) g_nbr[(size_t)ri * CAP + off] = (unsigned short)rj;
                }
                cnt += __popc(hb);
            }
        }
    }
    if (lane == 0) g_ncnt[ri] = min(cnt, CAP);
}

// ---------------- K6: rank-ordered fixed-point NMS resolve ----------------
// 2 bits per rank: bit0 = resolved, bit1 = kept
__global__ void __launch_bounds__(1024) k_resolve() {
    __shared__ unsigned long long state[NSTATE];
    __shared__ int more;
    int t = threadIdx.x;
    int kcnt = g_kcnt;
    for (int w = t; w < NSTATE; w += 1024) {
        int base = w << 5;
        unsigned long long sw = 0;
        for (int b = 0; b < 32; b++)
            if (base + b >= kcnt) sw |= 1ull << (2 * b);   // rank >= kcnt: resolved, not kept
        state[w] = sw;
    }
    if (t == 0) more = 0;
    __syncthreads();

    int chunk = (kcnt + 1023) >> 10;
    int lo = t * chunk, hi = min(lo + chunk, kcnt);
    bool mydone = (lo >= hi);
    for (;;) {
        int lm = 0;
        if (!mydone) {
            bool alldone = true;
            for (int r = lo; r < hi; r++) {
                unsigned long long sv = state[r >> 5] >> ((r & 31) * 2);
                if (sv & 1ull) continue;
                int cn = g_ncnt[r];
                const unsigned short* lst = g_nbr + (size_t)r * CAP;
                bool anyk = false, allres = true;
                for (int e = 0; e < cn; e++) {
                    int c = lst[e];
                    unsigned long long cs = state[c >> 5] >> ((c & 31) * 2);
                    if (cs & 2ull) { anyk = true; break; }
                    if (!(cs & 1ull)) allres = false;
                }
                if (anyk)
                    atomicOr(&state[r >> 5], 1ull << ((r & 31) * 2));
                else if (allres)
                    atomicOr(&state[r >> 5], 3ull << ((r & 31) * 2));
                else { lm = 1; alldone = false; }
            }
            mydone = alldone;
        }
        if (lm) more = 1;
        __syncthreads();
        int m = more;
        __syncthreads();
        if (!m) break;
        if (t == 0) more = 0;
        __syncthreads();
    }
    for (int w = t; w < NSTATE; w += 1024) g_state[w] = state[w];
}

// ---------------- K7: final masked write + hist re-zero for next replay ----------------
__global__ void k_final(float* __restrict__ out) {
    int i = blockIdx.x * blockDim.x + threadIdx.x;
    if (i < NDIG) g_hist[i] = 0;
    if (i >= N_ANCH) return;
    float sc = g_sc[i];
    int ri = g_srank[i];
    bool kp = false;
    if (ri != RINV) {
        unsigned long long sv = g_state[ri >> 5] >> ((ri & 31) * 2);
        kp = (sv & 2ull) != 0ull;
    }
    float f = kp ? 1.0f : 0.0f;
    out[i * 5 + 0] = __fmul_rn(g_x1[i], f);
    out[i * 5 + 1] = __fmul_rn(g_y1[i], f);
    out[i * 5 + 2] = __fmul_rn(g_x2[i], f);
    out[i * 5 + 3] = __fmul_rn(g_y2[i], f);
    out[i * 5 + 4] = __fmul_rn(sc, f);
}

extern "C" void kernel_launch(void* const* d_in, const int* in_sizes, int n_in,
                              void* d_out, int out_size) {
    (void)in_sizes; (void)n_in; (void)out_size;
    InPtrs p;
    for (int i = 0; i < 6; i++) {
        p.cls[i] = (const float*)d_in[2 * i];
        p.reg[i] = (const float*)d_in[2 * i + 1];
    }
    k_decode<<<NBLK, 256>>>(p);
    k_scan<<<1, 1024>>>();
    k_scatter<<<NBLK, 256>>>();
    k_binsort<<<NDIG / 8, 256>>>();
    k_nbr<<<(N_ANCH * 32 + 255) / 256, 256>>>();
    k_resolve<<<1, 1024>>>();
    k_final<<<NBLK, 256>>>((float*)d_out);
}

// round 10
// speedup vs baseline: 3.0027x; 1.4362x over previous
#include <cuda_runtime.h>
#include <math.h>

#define N_ANCH 21840
#define NWORDS 342            // ceil(21840/64) tiles
#define NSTATE 683            // ceil(21840/32), 2 bits per rank
#define NBLK   86             // ceil(21840/256)
#define NDIG   2048           // 11-bit digit space (valid keys only reach 0x7FF)
#define CAP    192            // max higher-rank suppressors per box
#define NRB    64             // resolve blocks
#define NRW    (NRB * 8)      // resolve warps
#define NMS_THF 0.3f
#define FIN_THF 0.5f
#define FULLM 0xFFFFFFFFu
#define RINV  0x7FFFFFFF      // rank sentinel for invalid boxes

// ---- static device scratch (zero at module load; g_hist/g_state re-zeroed per replay) ----
__device__ float g_x1[N_ANCH], g_y1[N_ANCH], g_x2[N_ANCH], g_y2[N_ANCH];
__device__ float g_sc[N_ANCH], g_area[N_ANCH];
__device__ unsigned g_key[N_ANCH];
__device__ int g_hist[NDIG];            // re-zeroed by k_final each replay
__device__ int g_base[NDIG], g_cursor[NDIG];
__device__ unsigned g_bin[N_ANCH];      // (low12 << 15) | idx
__device__ int g_srank[N_ANCH];         // RINV for invalid boxes
__device__ int g_kcnt;
__device__ float g_tminx1[NWORDS], g_tminy1[NWORDS], g_tmaxx2[NWORDS], g_tmaxy2[NWORDS];
__device__ float g_tamin[NWORDS], g_tamax[NWORDS];
__device__ unsigned short g_nbr[(size_t)N_ANCH * CAP];  // by rank
__device__ int g_ncnt[N_ANCH];                           // by rank
__device__ unsigned long long g_state[NSTATE];           // global: 2 bits/rank (resolved, kept)

struct InPtrs { const float* cls[6]; const float* reg[6]; };

// ---------------- K1: decode (bit-exact) + key + hist + tile bboxes ----------------
__global__ void k_decode(InPtrs in) {
    __shared__ float m0[256], m1[256], m2[256], m3[256], m4[256], m5[256];
    int t = threadIdx.x;
    int i = blockIdx.x * 256 + t;
    bool on = i < N_ANCH;

    float x1 = 0.f, y1 = 0.f, x2 = 0.f, y2 = 0.f, prob = 0.f, area = 0.f;
    if (on) {
        const int offs[7]   = {0, 16384, 20480, 21504, 21760, 21824, 21840};
        const int maps[6]   = {128, 64, 32, 16, 8, 4};
        const float strd[6] = {4.f, 8.f, 16.f, 32.f, 64.f, 128.f};
        int sc = 0;
        #pragma unroll
        for (int k = 0; k < 5; k++) if (i >= offs[k + 1]) sc = k + 1;
        int local = i - offs[sc];
        int W = maps[sc];
        int y = local / W, x = local - y * W;
        int HW = W * W;
        const float* cls = in.cls[sc];
        const float* reg = in.reg[sc];

        float c0 = cls[local], c1 = cls[HW + local];
        float m  = fmaxf(c0, c1);
        float e0 = expf(__fsub_rn(c0, m));
        float e1 = expf(__fsub_rn(c1, m));
        prob = __fdiv_rn(e1, __fadd_rn(e0, e1));

        float s   = strd[sc];
        float pwh = s * 4.0f;
        float pcx = __fadd_rn(0.5f * s, __fmul_rn((float)x, s));
        float pcy = __fadd_rn(0.5f * s, __fmul_rn((float)y, s));
        float l0 = reg[local], l1 = reg[HW + local];
        float l2 = reg[2 * HW + local], l3 = reg[3 * HW + local];
        float cx = __fadd_rn(pcx, __fmul_rn(__fmul_rn(l0, 0.1f), pwh));
        float cy = __fadd_rn(pcy, __fmul_rn(__fmul_rn(l1, 0.1f), pwh));
        float w  = __fmul_rn(pwh, expf(__fmul_rn(l2, 0.2f)));
        float h  = __fmul_rn(pwh, expf(__fmul_rn(l3, 0.2f)));
        x1 = __fsub_rn(cx, __fmul_rn(w, 0.5f));
        y1 = __fsub_rn(cy, __fmul_rn(h, 0.5f));
        x2 = __fadd_rn(x1, w);
        y2 = __fadd_rn(y1, h);
        area = __fmul_rn(__fadd_rn(__fsub_rn(x2, x1), 1.0f),
                         __fadd_rn(__fsub_rn(y2, y1), 1.0f));

        g_x1[i] = x1; g_y1[i] = y1; g_x2[i] = x2; g_y2[i] = y2;
        g_sc[i] = prob; g_area[i] = area;
        g_srank[i] = RINV;   // binsort overwrites for valid boxes

        // 24-bit key: prob in (0.5,1] -> [0, 0x7FFFFF]; ascending == descending score
        unsigned u   = __float_as_uint(prob);
        unsigned k24 = (~(u | 0x80000000u)) - 0x407FFFFFu;
        bool valid = prob > FIN_THF;
        g_key[i] = valid ? k24 : 0xFFFFFFFFu;
        if (valid) atomicAdd(&g_hist[k24 >> 12], 1);
    }

    // fused per-64 tile bboxes (valid boxes only)
    bool v = on && (prob > FIN_THF);
    m0[t] = v ? x1 :  1e30f;
    m1[t] = v ? y1 :  1e30f;
    m2[t] = v ? x2 : -1e30f;
    m3[t] = v ? y2 : -1e30f;
    m4[t] = v ? area :  1e30f;
    m5[t] = v ? area : -1e30f;
    int o = t & 63;
    for (int s = 32; s > 0; s >>= 1) {
        __syncthreads();
        if (o < s) {
            m0[t] = fminf(m0[t], m0[t + s]);
            m1[t] = fminf(m1[t], m1[t + s]);
            m2[t] = fmaxf(m2[t], m2[t + s]);
            m3[t] = fmaxf(m3[t], m3[t + s]);
            m4[t] = fminf(m4[t], m4[t + s]);
            m5[t] = fmaxf(m5[t], m5[t + s]);
        }
    }
    if (o == 0) {
        int tile = blockIdx.x * 4 + (t >> 6);
        if (tile < NWORDS) {
            g_tminx1[tile] = m0[t]; g_tminy1[tile] = m1[t];
            g_tmaxx2[tile] = m2[t]; g_tmaxy2[tile] = m3[t];
            g_tamin[tile]  = m4[t]; g_tamax[tile]  = m5[t];
        }
    }
}

// ---------------- K2: exclusive scan of 2048 digit counts ----------------
__global__ void __launch_bounds__(1024) k_scan() {
    __shared__ int wsum[32];
    int t = threadIdx.x, lane = t & 31, wid = t >> 5;
    int a0 = g_hist[2 * t], a1 = g_hist[2 * t + 1];
    int s = a0 + a1;
    int x = s;
    #pragma unroll
    for (int k = 1; k < 32; k <<= 1) { int y = __shfl_up_sync(FULLM, x, k); if (lane >= k) x += y; }
    if (lane == 31) wsum[wid] = x;
    __syncthreads();
    if (wid == 0) {
        int wv = wsum[lane];
        #pragma unroll
        for (int k = 1; k < 32; k <<= 1) { int y = __shfl_up_sync(FULLM, wv, k); if (lane >= k) wv += y; }
        wsum[lane] = wv;
    }
    __syncthreads();
    int base = x - s + ((wid > 0) ? wsum[wid - 1] : 0);
    g_base[2 * t] = base;          g_cursor[2 * t] = base;
    g_base[2 * t + 1] = base + a0; g_cursor[2 * t + 1] = base + a0;
    if (t == 1023) g_kcnt = base + s;   // total valid
}

// ---------------- K3: unstable scatter into bins (+ state zero for this replay) ----------------
__global__ void k_scatter() {
    if (blockIdx.x == 0) {
        for (int w = threadIdx.x; w < NSTATE; w += 256) g_state[w] = 0ull;
    }
    int i = blockIdx.x * 256 + threadIdx.x;
    if (i >= N_ANCH) return;
    unsigned k = g_key[i];
    if (k == 0xFFFFFFFFu) return;
    int d = k >> 12;
    int pos = atomicAdd(&g_cursor[d], 1);
    g_bin[pos] = ((k & 0xFFFu) << 15) | (unsigned)i;   // unique composite, stable order
}

// ---------------- K4: in-bin ranking (warp per bin) ----------------
__global__ void k_binsort() {
    int wid = threadIdx.x >> 5, lane = threadIdx.x & 31;
    int d = blockIdx.x * 8 + wid;
    if (d >= NDIG) return;
    int base = g_base[d];
    int n = g_cursor[d] - base;
    if (n == 0) return;
    if (n <= 32) {
        unsigned rec = (lane < n) ? g_bin[base + lane] : 0xFFFFFFFFu;
        int r = 0;
        for (int k = 0; k < n; k++) {
            unsigned other = __shfl_sync(FULLM, rec, k);
            r += (other < rec) ? 1 : 0;
        }
        if (lane < n) g_srank[rec & 0x7FFFu] = base + r;
    } else {
        for (int e = lane; e < n; e += 32) {
            unsigned rec = g_bin[base + e];
            int r = 0;
            for (int k = 0; k < n; k++) r += (g_bin[base + k] < rec) ? 1 : 0;
            g_srank[rec & 0x7FFFu] = base + r;
        }
    }
}

// ---------------- K5: sparse suppressor lists (warp per box, rank-indexed) ----------------
__global__ void k_nbr() {
    int i = (blockIdx.x * blockDim.x + threadIdx.x) >> 5;
    int lane = threadIdx.x & 31;
    if (i >= N_ANCH) return;
    int ri = g_srank[i];
    if (ri == RINV) return;   // invalid box (uniform per warp)
    float x1 = g_x1[i], y1 = g_y1[i], x2 = g_x2[i], y2 = g_y2[i], ai = g_area[i];
    int cnt = 0;
    for (int tb = 0; tb < NWORDS; tb += 32) {
        int t = tb + lane;
        bool act = false;
        if (t < NWORDS) {
            float bw = __fadd_rn(__fsub_rn(fminf(x2, g_tmaxx2[t]), fmaxf(x1, g_tminx1[t])), 1.0f);
            float bh = __fadd_rn(__fsub_rn(fminf(y2, g_tmaxy2[t]), fmaxf(y1, g_tminy1[t])), 1.0f);
            float lo = fminf(ai, g_tamax[t]);
            float hi = fmaxf(ai, g_tamin[t]);
            act = (bw > 0.f) && (bh > 0.f) && (lo > 0.299f * hi);  // conservative
        }
        unsigned bal = __ballot_sync(FULLM, act);
        while (bal) {
            int tt = __ffs(bal) - 1;
            bal &= bal - 1;
            int j0 = (tb + tt) << 6;
            #pragma unroll
            for (int h = 0; h < 2; h++) {
                int j = j0 + h * 32 + lane;
                bool hit = false;
                int rj = RINV;
                if (j < N_ANCH) {
                    rj = g_srank[j];
                    if (rj < ri) {   // sufficient: invalid j has rj == RINV
                        float xx1 = fmaxf(x1, g_x1[j]);
                        float yy1 = fmaxf(y1, g_y1[j]);
                        float xx2 = fminf(x2, g_x2[j]);
                        float yy2 = fminf(y2, g_y2[j]);
                        float w  = fmaxf(__fadd_rn(__fsub_rn(xx2, xx1), 1.f), 0.f);
                        float hh = fmaxf(__fadd_rn(__fsub_rn(yy2, yy1), 1.f), 0.f);
                        float inter = __fmul_rn(w, hh);
                        float aj = g_area[j];
                        if (inter > 0.299f * fmaxf(ai, aj)) {
                            float iou = __fdiv_rn(inter, __fsub_rn(__fadd_rn(ai, aj), inter));
                            hit = iou > NMS_THF;
                        }
                    }
                }
                unsigned hb = __ballot_sync(FULLM, hit);
                if (hit) {
                    int off = cnt + __popc(hb & ((1u << lane) - 1));
                    if (off < CAP) g_nbr[(size_t)ri * CAP + off] = (unsigned short)rj;
                }
                cnt += __popc(hb);
            }
        }
    }
    if (lane == 0) g_ncnt[ri] = min(cnt, CAP);
}

// ---------------- K6: dataflow NMS resolve (warp per rank, multi-SM, spin on deps) ----------------
// dependency edges always point to strictly lower ranks -> DAG -> no deadlock.
__global__ void __launch_bounds__(256) k_resolve() {
    int gw = (blockIdx.x * 256 + threadIdx.x) >> 5;
    int lane = threadIdx.x & 31;
    int kcnt = g_kcnt;
    for (int r = gw; r < kcnt; r += NRW) {
        int cn = g_ncnt[r];
        const unsigned short* lst = g_nbr + (size_t)r * CAP;
        bool removed = false;
        for (int b = 0; b < cn && !removed; b += 32) {
            int e = b + lane;
            int c = (e < cn) ? (int)lst[e] : 0;
            bool pend = (e < cn);
            bool kept = false;
            for (;;) {
                if (pend) {
                    unsigned long long w = *(volatile unsigned long long*)&g_state[c >> 5];
                    unsigned long long sv = w >> ((c & 31) * 2);
                    if (sv & 1ull) { kept = (sv & 2ull) != 0ull; pend = false; }
                }
                if (__ballot_sync(FULLM, kept)) { removed = true; break; }
                if (!__ballot_sync(FULLM, pend)) break;
                __nanosleep(32);
            }
        }
        if (lane == 0)
            atomicOr(&g_state[r >> 5], (removed ? 1ull : 3ull) << ((r & 31) * 2));
    }
}

// ---------------- K7: final masked write + hist re-zero for next replay ----------------
__global__ void k_final(float* __restrict__ out) {
    int i = blockIdx.x * blockDim.x + threadIdx.x;
    if (i < NDIG) g_hist[i] = 0;
    if (i >= N_ANCH) return;
    float sc = g_sc[i];
    int ri = g_srank[i];
    bool kp = false;
    if (ri != RINV) {
        unsigned long long sv = g_state[ri >> 5] >> ((ri & 31) * 2);
        kp = (sv & 2ull) != 0ull;
    }
    float f = kp ? 1.0f : 0.0f;
    out[i * 5 + 0] = __fmul_rn(g_x1[i], f);
    out[i * 5 + 1] = __fmul_rn(g_y1[i], f);
    out[i * 5 + 2] = __fmul_rn(g_x2[i], f);
    out[i * 5 + 3] = __fmul_rn(g_y2[i], f);
    out[i * 5 + 4] = __fmul_rn(sc, f);
}

extern "C" void kernel_launch(void* const* d_in, const int* in_sizes, int n_in,
                              void* d_out, int out_size) {
    (void)in_sizes; (void)n_in; (void)out_size;
    InPtrs p;
    for (int i = 0; i < 6; i++) {
        p.cls[i] = (const float*)d_in[2 * i];
        p.reg[i] = (const float*)d_in[2 * i + 1];
    }
    k_decode<<<NBLK, 256>>>(p);
    k_scan<<<1, 1024>>>();
    k_scatter<<<NBLK, 256>>>();
    k_binsort<<<NDIG / 8, 256>>>();
    k_nbr<<<(N_ANCH * 32 + 255) / 256, 256>>>();
    k_resolve<<<NRB, 256>>>();
    k_final<<<NBLK, 256>>>((float*)d_out);
}

// round 11
// speedup vs baseline: 3.5318x; 1.1762x over previous
#include <cuda_runtime.h>
#include <math.h>

#define N_ANCH 21840
#define NWORDS 342            // ceil(21840/64) tiles
#define NSTATE 683            // ceil(21840/32), 2 bits per rank
#define NBLK   86             // ceil(21840/256)
#define NDIG   2048           // 11-bit digit space (valid keys only reach 0x7FF)
#define CAP    192            // max higher-rank suppressors per box
#define NRB    64             // resolve blocks
#define NRW    (NRB * 8)      // resolve warps
#define NMS_THF 0.3f
#define FIN_THF 0.5f
#define FULLM 0xFFFFFFFFu
#define RINV  0x7FFFFFFF      // rank sentinel for invalid boxes

// ---- static device scratch (zero at module load; g_hist/g_state re-zeroed per replay) ----
__device__ float4 g_box[N_ANCH];        // x1,y1,x2,y2
__device__ float g_sc[N_ANCH];
__device__ unsigned g_key[N_ANCH];
__device__ int g_hist[NDIG];            // re-zeroed by k_final each replay
__device__ int g_base[NDIG], g_cursor[NDIG];
__device__ unsigned g_bin[N_ANCH];      // (low12 << 15) | idx
__device__ int g_srank[N_ANCH];         // RINV for invalid boxes
__device__ int g_kcnt;
__device__ float4 g_tbb[NWORDS];        // tile bbox: minx1,miny1,maxx2,maxy2
__device__ float2 g_tar[NWORDS];        // tile area: amin,amax
__device__ unsigned short g_nbr[(size_t)N_ANCH * CAP];  // by rank
__device__ int g_ncnt[N_ANCH];                           // by rank
__device__ unsigned long long g_state[NSTATE];           // global: 2 bits/rank (resolved, kept)

struct InPtrs { const float* cls[6]; const float* reg[6]; };

// exact area formula shared by all phases (bit-identical everywhere)
__device__ __forceinline__ float box_area(float x1, float y1, float x2, float y2) {
    return __fmul_rn(__fadd_rn(__fsub_rn(x2, x1), 1.0f),
                     __fadd_rn(__fsub_rn(y2, y1), 1.0f));
}

// ---------------- K1: decode (bit-exact) + key + hist + tile bboxes ----------------
__global__ void k_decode(InPtrs in) {
    __shared__ float m0[256], m1[256], m2[256], m3[256], m4[256], m5[256];
    int t = threadIdx.x;
    int i = blockIdx.x * 256 + t;
    bool on = i < N_ANCH;

    float x1 = 0.f, y1 = 0.f, x2 = 0.f, y2 = 0.f, prob = 0.f, area = 0.f;
    if (on) {
        const int offs[7]   = {0, 16384, 20480, 21504, 21760, 21824, 21840};
        const int maps[6]   = {128, 64, 32, 16, 8, 4};
        const float strd[6] = {4.f, 8.f, 16.f, 32.f, 64.f, 128.f};
        int sc = 0;
        #pragma unroll
        for (int k = 0; k < 5; k++) if (i >= offs[k + 1]) sc = k + 1;
        int local = i - offs[sc];
        int W = maps[sc];
        int y = local / W, x = local - y * W;
        int HW = W * W;
        const float* cls = in.cls[sc];
        const float* reg = in.reg[sc];

        float c0 = cls[local], c1 = cls[HW + local];
        float m  = fmaxf(c0, c1);
        float e0 = expf(__fsub_rn(c0, m));
        float e1 = expf(__fsub_rn(c1, m));
        prob = __fdiv_rn(e1, __fadd_rn(e0, e1));

        float s   = strd[sc];
        float pwh = s * 4.0f;
        float pcx = __fadd_rn(0.5f * s, __fmul_rn((float)x, s));
        float pcy = __fadd_rn(0.5f * s, __fmul_rn((float)y, s));
        float l0 = reg[local], l1 = reg[HW + local];
        float l2 = reg[2 * HW + local], l3 = reg[3 * HW + local];
        float cx = __fadd_rn(pcx, __fmul_rn(__fmul_rn(l0, 0.1f), pwh));
        float cy = __fadd_rn(pcy, __fmul_rn(__fmul_rn(l1, 0.1f), pwh));
        float w  = __fmul_rn(pwh, expf(__fmul_rn(l2, 0.2f)));
        float h  = __fmul_rn(pwh, expf(__fmul_rn(l3, 0.2f)));
        x1 = __fsub_rn(cx, __fmul_rn(w, 0.5f));
        y1 = __fsub_rn(cy, __fmul_rn(h, 0.5f));
        x2 = __fadd_rn(x1, w);
        y2 = __fadd_rn(y1, h);
        area = box_area(x1, y1, x2, y2);

        g_box[i] = make_float4(x1, y1, x2, y2);
        g_sc[i] = prob;
        g_srank[i] = RINV;   // binsort overwrites for valid boxes

        // 24-bit key: prob in (0.5,1] -> [0, 0x7FFFFF]; ascending == descending score
        unsigned u   = __float_as_uint(prob);
        unsigned k24 = (~(u | 0x80000000u)) - 0x407FFFFFu;
        bool valid = prob > FIN_THF;
        g_key[i] = valid ? k24 : 0xFFFFFFFFu;
        if (valid) atomicAdd(&g_hist[k24 >> 12], 1);
    }

    // fused per-64 tile bboxes (valid boxes only)
    bool v = on && (prob > FIN_THF);
    m0[t] = v ? x1 :  1e30f;
    m1[t] = v ? y1 :  1e30f;
    m2[t] = v ? x2 : -1e30f;
    m3[t] = v ? y2 : -1e30f;
    m4[t] = v ? area :  1e30f;
    m5[t] = v ? area : -1e30f;
    int o = t & 63;
    for (int s = 32; s > 0; s >>= 1) {
        __syncthreads();
        if (o < s) {
            m0[t] = fminf(m0[t], m0[t + s]);
            m1[t] = fminf(m1[t], m1[t + s]);
            m2[t] = fmaxf(m2[t], m2[t + s]);
            m3[t] = fmaxf(m3[t], m3[t + s]);
            m4[t] = fminf(m4[t], m4[t + s]);
            m5[t] = fmaxf(m5[t], m5[t + s]);
        }
    }
    if (o == 0) {
        int tile = blockIdx.x * 4 + (t >> 6);
        if (tile < NWORDS) {
            g_tbb[tile] = make_float4(m0[t], m1[t], m2[t], m3[t]);
            g_tar[tile] = make_float2(m4[t], m5[t]);
        }
    }
}

// ---------------- K2: exclusive scan of 2048 digit counts ----------------
__global__ void __launch_bounds__(1024) k_scan() {
    __shared__ int wsum[32];
    int t = threadIdx.x, lane = t & 31, wid = t >> 5;
    int a0 = g_hist[2 * t], a1 = g_hist[2 * t + 1];
    int s = a0 + a1;
    int x = s;
    #pragma unroll
    for (int k = 1; k < 32; k <<= 1) { int y = __shfl_up_sync(FULLM, x, k); if (lane >= k) x += y; }
    if (lane == 31) wsum[wid] = x;
    __syncthreads();
    if (wid == 0) {
        int wv = wsum[lane];
        #pragma unroll
        for (int k = 1; k < 32; k <<= 1) { int y = __shfl_up_sync(FULLM, wv, k); if (lane >= k) wv += y; }
        wsum[lane] = wv;
    }
    __syncthreads();
    int base = x - s + ((wid > 0) ? wsum[wid - 1] : 0);
    g_base[2 * t] = base;          g_cursor[2 * t] = base;
    g_base[2 * t + 1] = base + a0; g_cursor[2 * t + 1] = base + a0;
    if (t == 1023) g_kcnt = base + s;   // total valid
}

// ---------------- K3: unstable scatter into bins (+ state zero for this replay) ----------------
__global__ void k_scatter() {
    if (blockIdx.x == 0) {
        for (int w = threadIdx.x; w < NSTATE; w += 256) g_state[w] = 0ull;
    }
    int i = blockIdx.x * 256 + threadIdx.x;
    if (i >= N_ANCH) return;
    unsigned k = g_key[i];
    if (k == 0xFFFFFFFFu) return;
    int d = k >> 12;
    int pos = atomicAdd(&g_cursor[d], 1);
    g_bin[pos] = ((k & 0xFFFu) << 15) | (unsigned)i;   // unique composite, stable order
}

// ---------------- K4: in-bin ranking (warp per bin) ----------------
__global__ void k_binsort() {
    int wid = threadIdx.x >> 5, lane = threadIdx.x & 31;
    int d = blockIdx.x * 8 + wid;
    if (d >= NDIG) return;
    int base = g_base[d];
    int n = g_cursor[d] - base;
    if (n == 0) return;
    if (n <= 32) {
        unsigned rec = (lane < n) ? g_bin[base + lane] : 0xFFFFFFFFu;
        int r = 0;
        for (int k = 0; k < n; k++) {
            unsigned other = __shfl_sync(FULLM, rec, k);
            r += (other < rec) ? 1 : 0;
        }
        if (lane < n) g_srank[rec & 0x7FFFu] = base + r;
    } else {
        for (int e = lane; e < n; e += 32) {
            unsigned rec = g_bin[base + e];
            int r = 0;
            for (int k = 0; k < n; k++) r += (g_bin[base + k] < rec) ? 1 : 0;
            g_srank[rec & 0x7FFFu] = base + r;
        }
    }
}

// ---------------- K5: sparse suppressor lists (warp per box, rank-indexed) ----------------
__global__ void k_nbr() {
    int i = (blockIdx.x * blockDim.x + threadIdx.x) >> 5;
    int lane = threadIdx.x & 31;
    if (i >= N_ANCH) return;
    int ri = g_srank[i];
    if (ri == RINV) return;   // invalid box (uniform per warp)
    float4 bb = g_box[i];
    float x1 = bb.x, y1 = bb.y, x2 = bb.z, y2 = bb.w;
    float ai = box_area(x1, y1, x2, y2);
    int cnt = 0;
    for (int tb = 0; tb < NWORDS; tb += 32) {
        int t = tb + lane;
        bool act = false;
        if (t < NWORDS) {
            float4 tbv = g_tbb[t];
            float2 tav = g_tar[t];
            float bw = __fadd_rn(__fsub_rn(fminf(x2, tbv.z), fmaxf(x1, tbv.x)), 1.0f);
            float bh = __fadd_rn(__fsub_rn(fminf(y2, tbv.w), fmaxf(y1, tbv.y)), 1.0f);
            float lo = fminf(ai, tav.y);
            float hi = fmaxf(ai, tav.x);
            act = (bw > 0.f) && (bh > 0.f) && (lo > 0.299f * hi);  // conservative
        }
        unsigned bal = __ballot_sync(FULLM, act);
        while (bal) {
            int tt = __ffs(bal) - 1;
            bal &= bal - 1;
            int j0 = (tb + tt) << 6;
            #pragma unroll
            for (int h = 0; h < 2; h++) {
                int j = j0 + h * 32 + lane;
                bool hit = false;
                int rj = RINV;
                if (j < N_ANCH) {
                    rj = g_srank[j];
                    if (rj < ri) {   // sufficient: invalid j has rj == RINV
                        float4 bj = g_box[j];
                        float xx1 = fmaxf(x1, bj.x);
                        float yy1 = fmaxf(y1, bj.y);
                        float xx2 = fminf(x2, bj.z);
                        float yy2 = fminf(y2, bj.w);
                        float w  = fmaxf(__fadd_rn(__fsub_rn(xx2, xx1), 1.f), 0.f);
                        float hh = fmaxf(__fadd_rn(__fsub_rn(yy2, yy1), 1.f), 0.f);
                        float inter = __fmul_rn(w, hh);
                        float aj = box_area(bj.x, bj.y, bj.z, bj.w);
                        if (inter > 0.299f * fmaxf(ai, aj)) {
                            float iou = __fdiv_rn(inter, __fsub_rn(__fadd_rn(ai, aj), inter));
                            hit = iou > NMS_THF;
                        }
                    }
                }
                unsigned hb = __ballot_sync(FULLM, hit);
                if (hit) {
                    int off = cnt + __popc(hb & ((1u << lane) - 1));
                    if (off < CAP) g_nbr[(size_t)ri * CAP + off] = (unsigned short)rj;
                }
                cnt += __popc(hb);
            }
        }
    }
    if (lane == 0) g_ncnt[ri] = min(cnt, CAP);
}

// ---------------- K6: dataflow NMS resolve (warp per rank, multi-SM, spin on deps) ----------------
// dependency edges always point to strictly lower ranks -> DAG -> no deadlock.
__global__ void __launch_bounds__(256) k_resolve() {
    int gw = (blockIdx.x * 256 + threadIdx.x) >> 5;
    int lane = threadIdx.x & 31;
    int kcnt = g_kcnt;
    for (int r = gw; r < kcnt; r += NRW) {
        int cn = g_ncnt[r];
        const unsigned short* lst = g_nbr + (size_t)r * CAP;
        bool removed = false;
        for (int b = 0; b < cn && !removed; b += 32) {
            int e = b + lane;
            int c = (e < cn) ? (int)lst[e] : 0;
            bool pend = (e < cn);
            bool kept = false;
            for (;;) {
                if (pend) {
                    unsigned long long w = *(volatile unsigned long long*)&g_state[c >> 5];
                    unsigned long long sv = w >> ((c & 31) * 2);
                    if (sv & 1ull) { kept = (sv & 2ull) != 0ull; pend = false; }
                }
                if (__ballot_sync(FULLM, kept)) { removed = true; break; }
                if (!__ballot_sync(FULLM, pend)) break;
                __nanosleep(32);
            }
        }
        if (lane == 0)
            atomicOr(&g_state[r >> 5], (removed ? 1ull : 3ull) << ((r & 31) * 2));
    }
}

// ---------------- K7: final masked write + hist re-zero for next replay ----------------
__global__ void k_final(float* __restrict__ out) {
    int i = blockIdx.x * blockDim.x + threadIdx.x;
    if (i < NDIG) g_hist[i] = 0;
    if (i >= N_ANCH) return;
    float sc = g_sc[i];
    int ri = g_srank[i];
    bool kp = false;
    if (ri != RINV) {
        unsigned long long sv = g_state[ri >> 5] >> ((ri & 31) * 2);
        kp = (sv & 2ull) != 0ull;
    }
    float f = kp ? 1.0f : 0.0f;
    float4 bb = g_box[i];
    out[i * 5 + 0] = __fmul_rn(bb.x, f);
    out[i * 5 + 1] = __fmul_rn(bb.y, f);
    out[i * 5 + 2] = __fmul_rn(bb.z, f);
    out[i * 5 + 3] = __fmul_rn(bb.w, f);
    out[i * 5 + 4] = __fmul_rn(sc, f);
}

extern "C" void kernel_launch(void* const* d_in, const int* in_sizes, int n_in,
                              void* d_out, int out_size) {
    (void)in_sizes; (void)n_in; (void)out_size;
    InPtrs p;
    for (int i = 0; i < 6; i++) {
        p.cls[i] = (const float*)d_in[2 * i];
        p.reg[i] = (const float*)d_in[2 * i + 1];
    }
    k_decode<<<NBLK, 256>>>(p);
    k_scan<<<1, 1024>>>();
    k_scatter<<<NBLK, 256>>>();
    k_binsort<<<NDIG / 8, 256>>>();
    k_nbr<<<(N_ANCH * 32 + 255) / 256, 256>>>();
    k_resolve<<<NRB, 256>>>();
    k_final<<<NBLK, 256>>>((float*)d_out);
}

// round 12
// speedup vs baseline: 3.9025x; 1.1050x over previous
#include <cuda_runtime.h>
#include <math.h>

#define N_ANCH 21840
#define NTILE  683            // ceil(21840/32) tiles (one warp-width each)
#define NSTATE 683            // ceil(21840/32), 2 bits per rank
#define NBLK   86             // ceil(21840/256)
#define NDIG   2048           // 11-bit digit space (valid keys only reach 0x7FF)
#define CAP    192            // max higher-rank suppressors per box
#define NRB    64             // resolve blocks
#define NRW    (NRB * 8)      // resolve warps
#define NMS_THF 0.3f
#define FIN_THF 0.5f
#define FULLM 0xFFFFFFFFu
#define RINV  0x7FFFFFFF      // rank sentinel for invalid boxes

// ---- static device scratch (zero at module load; g_hist/g_state re-zeroed per replay) ----
__device__ float4 g_box[N_ANCH];        // x1,y1,x2,y2
__device__ float g_sc[N_ANCH];
__device__ unsigned g_key[N_ANCH];
__device__ int g_hist[NDIG];            // re-zeroed by k_resolve each replay
__device__ int g_base[NDIG], g_cursor[NDIG];
__device__ unsigned g_bin[N_ANCH];      // (low12 << 15) | idx
__device__ int g_srank[N_ANCH];         // RINV for invalid boxes
__device__ unsigned short g_ridx[N_ANCH];  // rank -> original index (valid ranks only)
__device__ int g_kcnt;
__device__ float4 g_tbb[NTILE];         // tile bbox: minx1,miny1,maxx2,maxy2
__device__ float2 g_tar[NTILE];         // tile area: amin,amax
__device__ unsigned short g_nbr[(size_t)N_ANCH * CAP];  // by rank
__device__ int g_ncnt[N_ANCH];                           // by rank
__device__ unsigned long long g_state[NSTATE];           // global: 2 bits/rank (resolved, kept)

struct InPtrs { const float* cls[6]; const float* reg[6]; };

// exact area formula shared by all phases (bit-identical everywhere)
__device__ __forceinline__ float box_area(float x1, float y1, float x2, float y2) {
    return __fmul_rn(__fadd_rn(__fsub_rn(x2, x1), 1.0f),
                     __fadd_rn(__fsub_rn(y2, y1), 1.0f));
}

// ---------------- K1: decode (bit-exact) + key + hist + warp tile bboxes + invalid-row zero ----------------
__global__ void k_decode(InPtrs in, float* __restrict__ out) {
    int t = threadIdx.x;
    int i = blockIdx.x * 256 + t;
    int lane = t & 31, wid = t >> 5;
    bool on = i < N_ANCH;

    float x1 = 0.f, y1 = 0.f, x2 = 0.f, y2 = 0.f, prob = 0.f, area = 0.f;
    if (on) {
        const int offs[7]   = {0, 16384, 20480, 21504, 21760, 21824, 21840};
        const int maps[6]   = {128, 64, 32, 16, 8, 4};
        const float strd[6] = {4.f, 8.f, 16.f, 32.f, 64.f, 128.f};
        int sc = 0;
        #pragma unroll
        for (int k = 0; k < 5; k++) if (i >= offs[k + 1]) sc = k + 1;
        int local = i - offs[sc];
        int W = maps[sc];
        int y = local / W, x = local - y * W;
        int HW = W * W;
        const float* cls = in.cls[sc];
        const float* reg = in.reg[sc];

        float c0 = cls[local], c1 = cls[HW + local];
        float m  = fmaxf(c0, c1);
        float e0 = expf(__fsub_rn(c0, m));
        float e1 = expf(__fsub_rn(c1, m));
        prob = __fdiv_rn(e1, __fadd_rn(e0, e1));

        float s   = strd[sc];
        float pwh = s * 4.0f;
        float pcx = __fadd_rn(0.5f * s, __fmul_rn((float)x, s));
        float pcy = __fadd_rn(0.5f * s, __fmul_rn((float)y, s));
        float l0 = reg[local], l1 = reg[HW + local];
        float l2 = reg[2 * HW + local], l3 = reg[3 * HW + local];
        float cx = __fadd_rn(pcx, __fmul_rn(__fmul_rn(l0, 0.1f), pwh));
        float cy = __fadd_rn(pcy, __fmul_rn(__fmul_rn(l1, 0.1f), pwh));
        float w  = __fmul_rn(pwh, expf(__fmul_rn(l2, 0.2f)));
        float h  = __fmul_rn(pwh, expf(__fmul_rn(l3, 0.2f)));
        x1 = __fsub_rn(cx, __fmul_rn(w, 0.5f));
        y1 = __fsub_rn(cy, __fmul_rn(h, 0.5f));
        x2 = __fadd_rn(x1, w);
        y2 = __fadd_rn(y1, h);
        area = box_area(x1, y1, x2, y2);

        g_box[i] = make_float4(x1, y1, x2, y2);
        g_sc[i] = prob;
        g_srank[i] = RINV;   // binsort overwrites for valid boxes

        // 24-bit key: prob in (0.5,1] -> [0, 0x7FFFFF]; ascending == descending score
        unsigned u   = __float_as_uint(prob);
        unsigned k24 = (~(u | 0x80000000u)) - 0x407FFFFFu;
        bool valid = prob > FIN_THF;
        g_key[i] = valid ? k24 : 0xFFFFFFFFu;
        if (valid) {
            atomicAdd(&g_hist[k24 >> 12], 1);
        } else {
            // invalid boxes are never kept: write their zero rows now
            out[i * 5 + 0] = 0.f; out[i * 5 + 1] = 0.f; out[i * 5 + 2] = 0.f;
            out[i * 5 + 3] = 0.f; out[i * 5 + 4] = 0.f;
        }
    }

    // fused per-32 (warp) tile bboxes over valid boxes, pure shuffle reduction
    bool v = on && (prob > FIN_THF);
    float r0 = v ? x1 :  1e30f;
    float r1 = v ? y1 :  1e30f;
    float r2 = v ? x2 : -1e30f;
    float r3 = v ? y2 : -1e30f;
    float r4 = v ? area :  1e30f;
    float r5 = v ? area : -1e30f;
    #pragma unroll
    for (int s = 16; s > 0; s >>= 1) {
        r0 = fminf(r0, __shfl_xor_sync(FULLM, r0, s));
        r1 = fminf(r1, __shfl_xor_sync(FULLM, r1, s));
        r2 = fmaxf(r2, __shfl_xor_sync(FULLM, r2, s));
        r3 = fmaxf(r3, __shfl_xor_sync(FULLM, r3, s));
        r4 = fminf(r4, __shfl_xor_sync(FULLM, r4, s));
        r5 = fmaxf(r5, __shfl_xor_sync(FULLM, r5, s));
    }
    if (lane == 0) {
        int tile = blockIdx.x * 8 + wid;
        if (tile < NTILE) {
            g_tbb[tile] = make_float4(r0, r1, r2, r3);
            g_tar[tile] = make_float2(r4, r5);
        }
    }
}

// ---------------- K2: exclusive scan of 2048 digit counts ----------------
__global__ void __launch_bounds__(1024) k_scan() {
    __shared__ int wsum[32];
    int t = threadIdx.x, lane = t & 31, wid = t >> 5;
    int a0 = g_hist[2 * t], a1 = g_hist[2 * t + 1];
    int s = a0 + a1;
    int x = s;
    #pragma unroll
    for (int k = 1; k < 32; k <<= 1) { int y = __shfl_up_sync(FULLM, x, k); if (lane >= k) x += y; }
    if (lane == 31) wsum[wid] = x;
    __syncthreads();
    if (wid == 0) {
        int wv = wsum[lane];
        #pragma unroll
        for (int k = 1; k < 32; k <<= 1) { int y = __shfl_up_sync(FULLM, wv, k); if (lane >= k) wv += y; }
        wsum[lane] = wv;
    }
    __syncthreads();
    int base = x - s + ((wid > 0) ? wsum[wid - 1] : 0);
    g_base[2 * t] = base;          g_cursor[2 * t] = base;
    g_base[2 * t + 1] = base + a0; g_cursor[2 * t + 1] = base + a0;
    if (t == 1023) g_kcnt = base + s;   // total valid
}

// ---------------- K3: unstable scatter into bins (+ state zero for this replay) ----------------
__global__ void k_scatter() {
    if (blockIdx.x == 0) {
        for (int w = threadIdx.x; w < NSTATE; w += 256) g_state[w] = 0ull;
    }
    int i = blockIdx.x * 256 + threadIdx.x;
    if (i >= N_ANCH) return;
    unsigned k = g_key[i];
    if (k == 0xFFFFFFFFu) return;
    int d = k >> 12;
    int pos = atomicAdd(&g_cursor[d], 1);
    g_bin[pos] = ((k & 0xFFFu) << 15) | (unsigned)i;   // unique composite, stable order
}

// ---------------- K4: in-bin ranking (warp per bin) ----------------
__global__ void k_binsort() {
    int wid = threadIdx.x >> 5, lane = threadIdx.x & 31;
    int d = blockIdx.x * 8 + wid;
    if (d >= NDIG) return;
    int base = g_base[d];
    int n = g_cursor[d] - base;
    if (n == 0) return;
    if (n <= 32) {
        unsigned rec = (lane < n) ? g_bin[base + lane] : 0xFFFFFFFFu;
        int r = 0;
        for (int k = 0; k < n; k++) {
            unsigned other = __shfl_sync(FULLM, rec, k);
            r += (other < rec) ? 1 : 0;
        }
        if (lane < n) {
            int idx = rec & 0x7FFFu;
            g_srank[idx] = base + r;
            g_ridx[base + r] = (unsigned short)idx;
        }
    } else {
        for (int e = lane; e < n; e += 32) {
            unsigned rec = g_bin[base + e];
            int r = 0;
            for (int k = 0; k < n; k++) r += (g_bin[base + k] < rec) ? 1 : 0;
            int idx = rec & 0x7FFFu;
            g_srank[idx] = base + r;
            g_ridx[base + r] = (unsigned short)idx;
        }
    }
}

// ---------------- K5: sparse suppressor lists (warp per box, 32-wide tiles) ----------------
__global__ void k_nbr() {
    int i = (blockIdx.x * blockDim.x + threadIdx.x) >> 5;
    int lane = threadIdx.x & 31;
    if (i >= N_ANCH) return;
    int ri = g_srank[i];
    if (ri == RINV) return;   // invalid box (uniform per warp)
    float4 bb = g_box[i];
    float x1 = bb.x, y1 = bb.y, x2 = bb.z, y2 = bb.w;
    float ai = box_area(x1, y1, x2, y2);
    int cnt = 0;
    for (int tb = 0; tb < NTILE; tb += 32) {
        int t = tb + lane;
        bool act = false;
        if (t < NTILE) {
            float4 tbv = g_tbb[t];
            float2 tav = g_tar[t];
            float bw = __fadd_rn(__fsub_rn(fminf(x2, tbv.z), fmaxf(x1, tbv.x)), 1.0f);
            float bh = __fadd_rn(__fsub_rn(fminf(y2, tbv.w), fmaxf(y1, tbv.y)), 1.0f);
            float lo = fminf(ai, tav.y);
            float hi = fmaxf(ai, tav.x);
            act = (bw > 0.f) && (bh > 0.f) && (lo > 0.299f * hi);  // conservative
        }
        unsigned bal = __ballot_sync(FULLM, act);
        while (bal) {
            int tt = __ffs(bal) - 1;
            bal &= bal - 1;
            int j = ((tb + tt) << 5) + lane;
            bool hit = false;
            int rj = RINV;
            if (j < N_ANCH) {
                rj = g_srank[j];
                if (rj < ri) {   // sufficient: invalid j has rj == RINV
                    float4 bj = g_box[j];
                    float xx1 = fmaxf(x1, bj.x);
                    float yy1 = fmaxf(y1, bj.y);
                    float xx2 = fminf(x2, bj.z);
                    float yy2 = fminf(y2, bj.w);
                    float w  = fmaxf(__fadd_rn(__fsub_rn(xx2, xx1), 1.f), 0.f);
                    float hh = fmaxf(__fadd_rn(__fsub_rn(yy2, yy1), 1.f), 0.f);
                    float inter = __fmul_rn(w, hh);
                    float aj = box_area(bj.x, bj.y, bj.z, bj.w);
                    if (inter > 0.299f * fmaxf(ai, aj)) {
                        float iou = __fdiv_rn(inter, __fsub_rn(__fadd_rn(ai, aj), inter));
                        hit = iou > NMS_THF;
                    }
                }
            }
            unsigned hb = __ballot_sync(FULLM, hit);
            if (hit) {
                int off = cnt + __popc(hb & ((1u << lane) - 1));
                if (off < CAP) g_nbr[(size_t)ri * CAP + off] = (unsigned short)rj;
            }
            cnt += __popc(hb);
        }
    }
    if (lane == 0) g_ncnt[ri] = min(cnt, CAP);
}

// ---------------- K6: dataflow NMS resolve + output write (+ hist re-zero) ----------------
// dependency edges always point to strictly lower ranks -> DAG -> no deadlock.
__global__ void __launch_bounds__(256) k_resolve(float* __restrict__ out) {
    int gid = blockIdx.x * 256 + threadIdx.x;
    if (gid < NDIG) g_hist[gid] = 0;   // reset for next replay
    int gw = gid >> 5;
    int lane = threadIdx.x & 31;
    int kcnt = g_kcnt;
    for (int r = gw; r < kcnt; r += NRW) {
        int cn = g_ncnt[r];
        const unsigned short* lst = g_nbr + (size_t)r * CAP;
        bool removed = false;
        for (int b = 0; b < cn && !removed; b += 32) {
            int e = b + lane;
            int c = (e < cn) ? (int)lst[e] : 0;
            bool pend = (e < cn);
            bool kept = false;
            for (;;) {
                if (pend) {
                    unsigned long long w = *(volatile unsigned long long*)&g_state[c >> 5];
                    unsigned long long sv = w >> ((c & 31) * 2);
                    if (sv & 1ull) { kept = (sv & 2ull) != 0ull; pend = false; }
                }
                if (__ballot_sync(FULLM, kept)) { removed = true; break; }
                if (!__ballot_sync(FULLM, pend)) break;
                __nanosleep(32);
            }
        }
        if (lane == 0) {
            atomicOr(&g_state[r >> 5], (removed ? 1ull : 3ull) << ((r & 31) * 2));
            // write this rank's output row immediately
            int idx = g_ridx[r];
            float f = removed ? 0.0f : 1.0f;
            float4 bb = g_box[idx];
            out[idx * 5 + 0] = __fmul_rn(bb.x, f);
            out[idx * 5 + 1] = __fmul_rn(bb.y, f);
            out[idx * 5 + 2] = __fmul_rn(bb.z, f);
            out[idx * 5 + 3] = __fmul_rn(bb.w, f);
            out[idx * 5 + 4] = __fmul_rn(g_sc[idx], f);
        }
    }
}

extern "C" void kernel_launch(void* const* d_in, const int* in_sizes, int n_in,
                              void* d_out, int out_size) {
    (void)in_sizes; (void)n_in; (void)out_size;
    InPtrs p;
    for (int i = 0; i < 6; i++) {
        p.cls[i] = (const float*)d_in[2 * i];
        p.reg[i] = (const float*)d_in[2 * i + 1];
    }
    float* out = (float*)d_out;
    k_decode<<<NBLK, 256>>>(p, out);
    k_scan<<<1, 1024>>>();
    k_scatter<<<NBLK, 256>>>();
    k_binsort<<<NDIG / 8, 256>>>();
    k_nbr<<<(N_ANCH * 32 + 255) / 256, 256>>>();
    k_resolve<<<NRB, 256>>>(out);
}

// round 13
// speedup vs baseline: 4.2762x; 1.0958x over previous
#include <cuda_runtime.h>
#include <math.h>

#define N_ANCH 21840
#define NCTILE 683            // max compacted tiles = ceil(21840/32)
#define NSTATE 683            // ceil(21840/32), 2 bits per rank
#define NBLK   86             // ceil(21840/256)
#define NDIG   2048           // 11-bit digit space (valid keys only reach 0x7FF)
#define CAP    192            // max higher-rank suppressors per box
#define NRB    64             // resolve blocks
#define NRW    (NRB * 8)      // resolve warps
#define NMS_THF 0.3f
#define FIN_THF 0.5f
#define FULLM 0xFFFFFFFFu

// ---- static device scratch (zero at module load; g_hist/g_state re-zeroed per replay) ----
__device__ float4 g_box[N_ANCH];        // x1,y1,x2,y2 (by original index)
__device__ float g_sc[N_ANCH];
__device__ unsigned g_key[N_ANCH];
__device__ int g_bcnt[NBLK], g_boff[NBLK];
__device__ int g_hist[NDIG];            // re-zeroed by k_resolve each replay
__device__ int g_base[NDIG], g_cursor[NDIG];
__device__ unsigned g_bin[N_ANCH];      // (low12 << 15) | cpos
__device__ float4 g_cbox[N_ANCH];       // compacted valid boxes (index order)
__device__ unsigned short g_cidx[N_ANCH];  // cpos -> original index
__device__ int g_crank[N_ANCH];           // cpos -> rank
__device__ unsigned short g_ridx[N_ANCH];  // rank -> original index
__device__ int g_kcnt;
__device__ float4 g_tbb[NCTILE];        // compacted tile bbox
__device__ float2 g_tar[NCTILE];        // compacted tile area min/max
__device__ unsigned short g_nbr[(size_t)N_ANCH * CAP];  // by rank
__device__ int g_ncnt[N_ANCH];                           // by rank
__device__ unsigned long long g_state[NSTATE];           // 2 bits/rank (resolved, kept)

struct InPtrs { const float* cls[6]; const float* reg[6]; };

// exact area formula shared by all phases (bit-identical everywhere)
__device__ __forceinline__ float box_area(float x1, float y1, float x2, float y2) {
    return __fmul_rn(__fadd_rn(__fsub_rn(x2, x1), 1.0f),
                     __fadd_rn(__fsub_rn(y2, y1), 1.0f));
}

// ---------------- K1: decode (bit-exact) + key + hist + block valid count ----------------
__global__ void k_decode(InPtrs in, float* __restrict__ out) {
    __shared__ int bc;
    int t = threadIdx.x;
    int i = blockIdx.x * 256 + t;
    int lane = t & 31;
    bool on = i < N_ANCH;
    if (t == 0) bc = 0;
    __syncthreads();

    bool valid = false;
    if (on) {
        const int offs[7]   = {0, 16384, 20480, 21504, 21760, 21824, 21840};
        const int maps[6]   = {128, 64, 32, 16, 8, 4};
        const float strd[6] = {4.f, 8.f, 16.f, 32.f, 64.f, 128.f};
        int sc = 0;
        #pragma unroll
        for (int k = 0; k < 5; k++) if (i >= offs[k + 1]) sc = k + 1;
        int local = i - offs[sc];
        int W = maps[sc];
        int y = local / W, x = local - y * W;
        int HW = W * W;
        const float* cls = in.cls[sc];
        const float* reg = in.reg[sc];

        float c0 = cls[local], c1 = cls[HW + local];
        float m  = fmaxf(c0, c1);
        float e0 = expf(__fsub_rn(c0, m));
        float e1 = expf(__fsub_rn(c1, m));
        float prob = __fdiv_rn(e1, __fadd_rn(e0, e1));

        float s   = strd[sc];
        float pwh = s * 4.0f;
        float pcx = __fadd_rn(0.5f * s, __fmul_rn((float)x, s));
        float pcy = __fadd_rn(0.5f * s, __fmul_rn((float)y, s));
        float l0 = reg[local], l1 = reg[HW + local];
        float l2 = reg[2 * HW + local], l3 = reg[3 * HW + local];
        float cx = __fadd_rn(pcx, __fmul_rn(__fmul_rn(l0, 0.1f), pwh));
        float cy = __fadd_rn(pcy, __fmul_rn(__fmul_rn(l1, 0.1f), pwh));
        float w  = __fmul_rn(pwh, expf(__fmul_rn(l2, 0.2f)));
        float h  = __fmul_rn(pwh, expf(__fmul_rn(l3, 0.2f)));
        float x1 = __fsub_rn(cx, __fmul_rn(w, 0.5f));
        float y1 = __fsub_rn(cy, __fmul_rn(h, 0.5f));
        float x2 = __fadd_rn(x1, w);
        float y2 = __fadd_rn(y1, h);

        g_box[i] = make_float4(x1, y1, x2, y2);
        g_sc[i] = prob;

        // 24-bit key: prob in (0.5,1] -> [0, 0x7FFFFF]; ascending == descending score
        unsigned u   = __float_as_uint(prob);
        unsigned k24 = (~(u | 0x80000000u)) - 0x407FFFFFu;
        valid = prob > FIN_THF;
        g_key[i] = valid ? k24 : 0xFFFFFFFFu;
        if (valid) {
            atomicAdd(&g_hist[k24 >> 12], 1);
        } else {
            // invalid boxes are never kept: write their zero rows now
            out[i * 5 + 0] = 0.f; out[i * 5 + 1] = 0.f; out[i * 5 + 2] = 0.f;
            out[i * 5 + 3] = 0.f; out[i * 5 + 4] = 0.f;
        }
    }
    unsigned bal = __ballot_sync(FULLM, valid);
    if (lane == 0) atomicAdd(&bc, __popc(bal));
    __syncthreads();
    if (t == 0) g_bcnt[blockIdx.x] = bc;
}

// ---------------- K2: exclusive scans (2048 digits + 86 block counts) ----------------
__global__ void __launch_bounds__(1024) k_scan() {
    __shared__ int wsum[32];
    int t = threadIdx.x, lane = t & 31, wid = t >> 5;

    // side job (warp 1): exclusive scan of 86 per-block valid counts
    if (wid == 1) {
        int v0 = (lane < NBLK) ? g_bcnt[lane] : 0;
        int v1 = (lane + 32 < NBLK) ? g_bcnt[lane + 32] : 0;
        int v2 = (lane + 64 < NBLK) ? g_bcnt[lane + 64] : 0;
        int s0 = v0, s1 = v1, s2 = v2;
        #pragma unroll
        for (int k = 1; k < 32; k <<= 1) {
            int a = __shfl_up_sync(FULLM, s0, k); if (lane >= k) s0 += a;
            int b = __shfl_up_sync(FULLM, s1, k); if (lane >= k) s1 += b;
            int c = __shfl_up_sync(FULLM, s2, k); if (lane >= k) s2 += c;
        }
        int t0 = __shfl_sync(FULLM, s0, 31);
        int t1 = __shfl_sync(FULLM, s1, 31);
        if (lane < NBLK) g_boff[lane] = s0 - v0;
        if (lane + 32 < NBLK) g_boff[lane + 32] = t0 + s1 - v1;
        if (lane + 64 < NBLK) g_boff[lane + 64] = t0 + t1 + s2 - v2;
    }

    int a0 = g_hist[2 * t], a1 = g_hist[2 * t + 1];
    int s = a0 + a1;
    int x = s;
    #pragma unroll
    for (int k = 1; k < 32; k <<= 1) { int y = __shfl_up_sync(FULLM, x, k); if (lane >= k) x += y; }
    if (lane == 31) wsum[wid] = x;
    __syncthreads();
    if (wid == 0) {
        int wv = wsum[lane];
        #pragma unroll
        for (int k = 1; k < 32; k <<= 1) { int y = __shfl_up_sync(FULLM, wv, k); if (lane >= k) wv += y; }
        wsum[lane] = wv;
    }
    __syncthreads();
    int base = x - s + ((wid > 0) ? wsum[wid - 1] : 0);
    g_base[2 * t] = base;          g_cursor[2 * t] = base;
    g_base[2 * t + 1] = base + a0; g_cursor[2 * t + 1] = base + a0;
    if (t == 1023) g_kcnt = base + s;   // total valid
}

// ---------------- K3: bin scatter + ordered compaction (+ state zero) ----------------
__global__ void k_scatter() {
    __shared__ int wscan[8];
    if (blockIdx.x == 0) {
        for (int w = threadIdx.x; w < NSTATE; w += 256) g_state[w] = 0ull;
    }
    int t = threadIdx.x, lane = t & 31, wid = t >> 5;
    int i = blockIdx.x * 256 + t;
    bool on = i < N_ANCH;
    unsigned k = on ? g_key[i] : 0xFFFFFFFFu;
    bool valid = (k != 0xFFFFFFFFu);

    unsigned bal = __ballot_sync(FULLM, valid);
    if (lane == 0) wscan[wid] = __popc(bal);
    __syncthreads();
    if (t == 0) {
        int run = 0;
        #pragma unroll
        for (int w = 0; w < 8; w++) { int c = wscan[w]; wscan[w] = run; run += c; }
    }
    __syncthreads();

    if (valid) {
        int cpos = g_boff[blockIdx.x] + wscan[wid] + __popc(bal & ((1u << lane) - 1));
        g_cbox[cpos] = g_box[i];
        g_cidx[cpos] = (unsigned short)i;
        int d = k >> 12;
        int pos = atomicAdd(&g_cursor[d], 1);
        g_bin[pos] = ((k & 0xFFFu) << 15) | (unsigned)cpos;   // cpos monotone in idx -> stable ties
    }
}

// ---------------- K4: in-bin ranking (warp per bin) + compacted tile bboxes ----------------
__global__ void k_binsort() {
    int wid = threadIdx.x >> 5, lane = threadIdx.x & 31;
    int gw = blockIdx.x * 8 + wid;
    if (gw < NDIG) {
        int d = gw;
        int base = g_base[d];
        int n = g_cursor[d] - base;
        if (n == 0) return;
        if (n <= 32) {
            unsigned rec = (lane < n) ? g_bin[base + lane] : 0xFFFFFFFFu;
            int r = 0;
            for (int k = 0; k < n; k++) {
                unsigned other = __shfl_sync(FULLM, rec, k);
                r += (other < rec) ? 1 : 0;
            }
            if (lane < n) {
                int cpos = rec & 0x7FFFu;
                int rank = base + r;
                g_crank[cpos] = rank;
                g_ridx[rank] = g_cidx[cpos];
            }
        } else {
            for (int e = lane; e < n; e += 32) {
                unsigned rec = g_bin[base + e];
                int r = 0;
                for (int k = 0; k < n; k++) r += (g_bin[base + k] < rec) ? 1 : 0;
                int cpos = rec & 0x7FFFu;
                int rank = base + r;
                g_crank[cpos] = rank;
                g_ridx[rank] = g_cidx[cpos];
            }
        }
    } else {
        // tile-bbox warps over the compacted array
        int tile = gw - NDIG;
        if (tile >= NCTILE) return;
        int kcnt = g_kcnt;
        int kk = tile * 32 + lane;
        bool on = kk < kcnt;
        float x1 = 0.f, y1 = 0.f, x2 = 0.f, y2 = 0.f, area = 0.f;
        if (on) {
            float4 b = g_cbox[kk];
            x1 = b.x; y1 = b.y; x2 = b.z; y2 = b.w;
            area = box_area(x1, y1, x2, y2);
        }
        float r0 = on ? x1 :  1e30f;
        float r1 = on ? y1 :  1e30f;
        float r2 = on ? x2 : -1e30f;
        float r3 = on ? y2 : -1e30f;
        float r4 = on ? area :  1e30f;
        float r5 = on ? area : -1e30f;
        #pragma unroll
        for (int s = 16; s > 0; s >>= 1) {
            r0 = fminf(r0, __shfl_xor_sync(FULLM, r0, s));
            r1 = fminf(r1, __shfl_xor_sync(FULLM, r1, s));
            r2 = fmaxf(r2, __shfl_xor_sync(FULLM, r2, s));
            r3 = fmaxf(r3, __shfl_xor_sync(FULLM, r3, s));
            r4 = fminf(r4, __shfl_xor_sync(FULLM, r4, s));
            r5 = fmaxf(r5, __shfl_xor_sync(FULLM, r5, s));
        }
        if (lane == 0) {
            g_tbb[tile] = make_float4(r0, r1, r2, r3);
            g_tar[tile] = make_float2(r4, r5);
        }
    }
}

// ---------------- K5: sparse suppressor lists (warp per compacted box) ----------------
__global__ void k_nbr() {
    int kq = (blockIdx.x * blockDim.x + threadIdx.x) >> 5;
    int lane = threadIdx.x & 31;
    int kcnt = g_kcnt;
    if (kq >= kcnt) return;
    int ri = g_crank[kq];
    float4 bb = g_cbox[kq];
    float x1 = bb.x, y1 = bb.y, x2 = bb.z, y2 = bb.w;
    float ai = box_area(x1, y1, x2, y2);
    int ntile = (kcnt + 31) >> 5;
    int cnt = 0;
    for (int tb = 0; tb < ntile; tb += 32) {
        int t = tb + lane;
        bool act = false;
        if (t < ntile) {
            float4 tbv = g_tbb[t];
            float2 tav = g_tar[t];
            float bw = __fadd_rn(__fsub_rn(fminf(x2, tbv.z), fmaxf(x1, tbv.x)), 1.0f);
            float bh = __fadd_rn(__fsub_rn(fminf(y2, tbv.w), fmaxf(y1, tbv.y)), 1.0f);
            float lo = fminf(ai, tav.y);
            float hi = fmaxf(ai, tav.x);
            act = (bw > 0.f) && (bh > 0.f) && (lo > 0.299f * hi);  // conservative
        }
        unsigned bal = __ballot_sync(FULLM, act);
        while (bal) {
            int tt = __ffs(bal) - 1;
            bal &= bal - 1;
            int j = ((tb + tt) << 5) + lane;
            bool hit = false;
            int rj = 0x7FFFFFFF;
            if (j < kcnt) {
                rj = g_crank[j];
                if (rj < ri) {
                    float4 bj = g_cbox[j];
                    float xx1 = fmaxf(x1, bj.x);
                    float yy1 = fmaxf(y1, bj.y);
                    float xx2 = fminf(x2, bj.z);
                    float yy2 = fminf(y2, bj.w);
                    float w  = fmaxf(__fadd_rn(__fsub_rn(xx2, xx1), 1.f), 0.f);
                    float hh = fmaxf(__fadd_rn(__fsub_rn(yy2, yy1), 1.f), 0.f);
                    float inter = __fmul_rn(w, hh);
                    float aj = box_area(bj.x, bj.y, bj.z, bj.w);
                    if (inter > 0.299f * fmaxf(ai, aj)) {
                        float iou = __fdiv_rn(inter, __fsub_rn(__fadd_rn(ai, aj), inter));
                        hit = iou > NMS_THF;
                    }
                }
            }
            unsigned hb = __ballot_sync(FULLM, hit);
            if (hit) {
                int off = cnt + __popc(hb & ((1u << lane) - 1));
                if (off < CAP) g_nbr[(size_t)ri * CAP + off] = (unsigned short)rj;
            }
            cnt += __popc(hb);
        }
    }
    if (lane == 0) g_ncnt[ri] = min(cnt, CAP);
}

// ---------------- K6: dataflow NMS resolve + output write (+ hist re-zero) ----------------
// dependency edges always point to strictly lower ranks -> DAG -> no deadlock.
__global__ void __launch_bounds__(256) k_resolve(float* __restrict__ out) {
    int gid = blockIdx.x * 256 + threadIdx.x;
    if (gid < NDIG) g_hist[gid] = 0;   // reset for next replay
    int gw = gid >> 5;
    int lane = threadIdx.x & 31;
    int kcnt = g_kcnt;
    for (int r = gw; r < kcnt; r += NRW) {
        int cn = g_ncnt[r];
        const unsigned short* lst = g_nbr + (size_t)r * CAP;
        bool removed = false;
        for (int b = 0; b < cn && !removed; b += 32) {
            int e = b + lane;
            int c = (e < cn) ? (int)lst[e] : 0;
            bool pend = (e < cn);
            bool kept = false;
            for (;;) {
                if (pend) {
                    unsigned long long w = *(volatile unsigned long long*)&g_state[c >> 5];
                    unsigned long long sv = w >> ((c & 31) * 2);
                    if (sv & 1ull) { kept = (sv & 2ull) != 0ull; pend = false; }
                }
                if (__ballot_sync(FULLM, kept)) { removed = true; break; }
                if (!__ballot_sync(FULLM, pend)) break;
                __nanosleep(32);
            }
        }
        if (lane == 0) {
            atomicOr(&g_state[r >> 5], (removed ? 1ull : 3ull) << ((r & 31) * 2));
            int idx = g_ridx[r];
            float f = removed ? 0.0f : 1.0f;
            float4 bb = g_box[idx];
            out[idx * 5 + 0] = __fmul_rn(bb.x, f);
            out[idx * 5 + 1] = __fmul_rn(bb.y, f);
            out[idx * 5 + 2] = __fmul_rn(bb.z, f);
            out[idx * 5 + 3] = __fmul_rn(bb.w, f);
            out[idx * 5 + 4] = __fmul_rn(g_sc[idx], f);
        }
    }
}

extern "C" void kernel_launch(void* const* d_in, const int* in_sizes, int n_in,
                              void* d_out, int out_size) {
    (void)in_sizes; (void)n_in; (void)out_size;
    InPtrs p;
    for (int i = 0; i < 6; i++) {
        p.cls[i] = (const float*)d_in[2 * i];
        p.reg[i] = (const float*)d_in[2 * i + 1];
    }
    float* out = (float*)d_out;
    k_decode<<<NBLK, 256>>>(p, out);
    k_scan<<<1, 1024>>>();
    k_scatter<<<NBLK, 256>>>();
    k_binsort<<<NDIG / 8 + (NCTILE + 7) / 8, 256>>>();
    k_nbr<<<(N_ANCH * 32 + 255) / 256, 256>>>();
    k_resolve<<<NRB, 256>>>(out);
}

// round 14
// speedup vs baseline: 4.3131x; 1.0086x over previous
#include <cuda_runtime.h>
#include <math.h>

#define N_ANCH 21840
#define NCTILE 683            // max compacted tiles = ceil(21840/32)
#define NSTATE 683            // ceil(21840/32), 2 bits per rank
#define NBLK   86             // ceil(21840/256)
#define NDIG   2048           // 11-bit digit space (valid keys only reach 0x7FF)
#define CAP    192            // max higher-rank suppressors per box
#define NRB    64             // resolve blocks
#define NRW    (NRB * 8)      // resolve warps
#define NMS_THF 0.3f
#define FIN_THF 0.5f
#define FULLM 0xFFFFFFFFu

// ---- static device scratch (zero at module load; g_hist/g_state re-zeroed per replay) ----
__device__ float4 g_box[N_ANCH];        // x1,y1,x2,y2 (by original index)
__device__ float g_sc[N_ANCH];
__device__ unsigned g_key[N_ANCH];
__device__ int g_bcnt[NBLK], g_boff[NBLK];
__device__ int g_hist[NDIG];            // re-zeroed by k_resolve each replay
__device__ int g_base[NDIG], g_cursor[NDIG];
__device__ unsigned g_bin[N_ANCH];      // (low12 << 15) | cpos
__device__ float4 g_cbox[N_ANCH];       // compacted valid boxes (index order)
__device__ float2 g_cra[N_ANCH];        // cpos -> (area, rank-as-int-bits)
__device__ unsigned short g_cidx[N_ANCH];  // cpos -> original index
__device__ unsigned short g_ridx[N_ANCH];  // rank -> original index
__device__ int g_kcnt;
__device__ float4 g_tbb[NCTILE];        // compacted tile bbox
__device__ float2 g_tar[NCTILE];        // compacted tile area min/max
__device__ unsigned short g_nbr[(size_t)N_ANCH * CAP];  // by rank
__device__ int g_ncnt[N_ANCH];                           // by rank
__device__ unsigned long long g_state[NSTATE];           // 2 bits/rank (resolved, kept)

struct InPtrs { const float* cls[6]; const float* reg[6]; };

// exact area formula shared by all phases (bit-identical everywhere)
__device__ __forceinline__ float box_area(float x1, float y1, float x2, float y2) {
    return __fmul_rn(__fadd_rn(__fsub_rn(x2, x1), 1.0f),
                     __fadd_rn(__fsub_rn(y2, y1), 1.0f));
}

// ---------------- K1: decode (bit-exact) + key + hist + block valid count ----------------
__global__ void k_decode(InPtrs in, float* __restrict__ out) {
    __shared__ int bc;
    int t = threadIdx.x;
    int i = blockIdx.x * 256 + t;
    int lane = t & 31;
    bool on = i < N_ANCH;
    if (t == 0) bc = 0;
    __syncthreads();

    bool valid = false;
    if (on) {
        const int offs[7]   = {0, 16384, 20480, 21504, 21760, 21824, 21840};
        const int maps[6]   = {128, 64, 32, 16, 8, 4};
        const float strd[6] = {4.f, 8.f, 16.f, 32.f, 64.f, 128.f};
        int sc = 0;
        #pragma unroll
        for (int k = 0; k < 5; k++) if (i >= offs[k + 1]) sc = k + 1;
        int local = i - offs[sc];
        int W = maps[sc];
        int y = local / W, x = local - y * W;
        int HW = W * W;
        const float* cls = in.cls[sc];
        const float* reg = in.reg[sc];

        float c0 = cls[local], c1 = cls[HW + local];
        float m  = fmaxf(c0, c1);
        float e0 = expf(__fsub_rn(c0, m));
        float e1 = expf(__fsub_rn(c1, m));
        float prob = __fdiv_rn(e1, __fadd_rn(e0, e1));

        float s   = strd[sc];
        float pwh = s * 4.0f;
        float pcx = __fadd_rn(0.5f * s, __fmul_rn((float)x, s));
        float pcy = __fadd_rn(0.5f * s, __fmul_rn((float)y, s));
        float l0 = reg[local], l1 = reg[HW + local];
        float l2 = reg[2 * HW + local], l3 = reg[3 * HW + local];
        float cx = __fadd_rn(pcx, __fmul_rn(__fmul_rn(l0, 0.1f), pwh));
        float cy = __fadd_rn(pcy, __fmul_rn(__fmul_rn(l1, 0.1f), pwh));
        float w  = __fmul_rn(pwh, expf(__fmul_rn(l2, 0.2f)));
        float h  = __fmul_rn(pwh, expf(__fmul_rn(l3, 0.2f)));
        float x1 = __fsub_rn(cx, __fmul_rn(w, 0.5f));
        float y1 = __fsub_rn(cy, __fmul_rn(h, 0.5f));
        float x2 = __fadd_rn(x1, w);
        float y2 = __fadd_rn(y1, h);

        g_box[i] = make_float4(x1, y1, x2, y2);
        g_sc[i] = prob;

        // 24-bit key: prob in (0.5,1] -> [0, 0x7FFFFF]; ascending == descending score
        unsigned u   = __float_as_uint(prob);
        unsigned k24 = (~(u | 0x80000000u)) - 0x407FFFFFu;
        valid = prob > FIN_THF;
        g_key[i] = valid ? k24 : 0xFFFFFFFFu;
        if (valid) {
            atomicAdd(&g_hist[k24 >> 12], 1);
        } else {
            // invalid boxes are never kept: write their zero rows now
            out[i * 5 + 0] = 0.f; out[i * 5 + 1] = 0.f; out[i * 5 + 2] = 0.f;
            out[i * 5 + 3] = 0.f; out[i * 5 + 4] = 0.f;
        }
    }
    unsigned bal = __ballot_sync(FULLM, valid);
    if (lane == 0) atomicAdd(&bc, __popc(bal));
    __syncthreads();
    if (t == 0) g_bcnt[blockIdx.x] = bc;
}

// ---------------- K2: exclusive scans (2048 digits + 86 block counts) ----------------
__global__ void __launch_bounds__(1024) k_scan() {
    __shared__ int wsum[32];
    int t = threadIdx.x, lane = t & 31, wid = t >> 5;

    // side job (warp 1): exclusive scan of 86 per-block valid counts
    if (wid == 1) {
        int v0 = (lane < NBLK) ? g_bcnt[lane] : 0;
        int v1 = (lane + 32 < NBLK) ? g_bcnt[lane + 32] : 0;
        int v2 = (lane + 64 < NBLK) ? g_bcnt[lane + 64] : 0;
        int s0 = v0, s1 = v1, s2 = v2;
        #pragma unroll
        for (int k = 1; k < 32; k <<= 1) {
            int a = __shfl_up_sync(FULLM, s0, k); if (lane >= k) s0 += a;
            int b = __shfl_up_sync(FULLM, s1, k); if (lane >= k) s1 += b;
            int c = __shfl_up_sync(FULLM, s2, k); if (lane >= k) s2 += c;
        }
        int t0 = __shfl_sync(FULLM, s0, 31);
        int t1 = __shfl_sync(FULLM, s1, 31);
        if (lane < NBLK) g_boff[lane] = s0 - v0;
        if (lane + 32 < NBLK) g_boff[lane + 32] = t0 + s1 - v1;
        if (lane + 64 < NBLK) g_boff[lane + 64] = t0 + t1 + s2 - v2;
    }

    int a0 = g_hist[2 * t], a1 = g_hist[2 * t + 1];
    int s = a0 + a1;
    int x = s;
    #pragma unroll
    for (int k = 1; k < 32; k <<= 1) { int y = __shfl_up_sync(FULLM, x, k); if (lane >= k) x += y; }
    if (lane == 31) wsum[wid] = x;
    __syncthreads();
    if (wid == 0) {
        int wv = wsum[lane];
        #pragma unroll
        for (int k = 1; k < 32; k <<= 1) { int y = __shfl_up_sync(FULLM, wv, k); if (lane >= k) wv += y; }
        wsum[lane] = wv;
    }
    __syncthreads();
    int base = x - s + ((wid > 0) ? wsum[wid - 1] : 0);
    g_base[2 * t] = base;          g_cursor[2 * t] = base;
    g_base[2 * t + 1] = base + a0; g_cursor[2 * t + 1] = base + a0;
    if (t == 1023) g_kcnt = base + s;   // total valid
}

// ---------------- K3: bin scatter + ordered compaction (+ state zero) ----------------
__global__ void k_scatter() {
    __shared__ int wscan[8];
    if (blockIdx.x == 0) {
        for (int w = threadIdx.x; w < NSTATE; w += 256) g_state[w] = 0ull;
    }
    int t = threadIdx.x, lane = t & 31, wid = t >> 5;
    int i = blockIdx.x * 256 + t;
    bool on = i < N_ANCH;
    unsigned k = on ? g_key[i] : 0xFFFFFFFFu;
    bool valid = (k != 0xFFFFFFFFu);

    unsigned bal = __ballot_sync(FULLM, valid);
    if (lane == 0) wscan[wid] = __popc(bal);
    __syncthreads();
    if (t == 0) {
        int run = 0;
        #pragma unroll
        for (int w = 0; w < 8; w++) { int c = wscan[w]; wscan[w] = run; run += c; }
    }
    __syncthreads();

    if (valid) {
        int cpos = g_boff[blockIdx.x] + wscan[wid] + __popc(bal & ((1u << lane) - 1));
        float4 b = g_box[i];
        g_cbox[cpos] = b;
        g_cra[cpos] = make_float2(box_area(b.x, b.y, b.z, b.w), 0.f);  // rank patched by binsort
        g_cidx[cpos] = (unsigned short)i;
        int d = k >> 12;
        int pos = atomicAdd(&g_cursor[d], 1);
        g_bin[pos] = ((k & 0xFFFu) << 15) | (unsigned)cpos;   // cpos monotone in idx -> stable ties
    }
}

// ---------------- K4: in-bin ranking (warp per bin) + compacted tile bboxes ----------------
__global__ void k_binsort() {
    int wid = threadIdx.x >> 5, lane = threadIdx.x & 31;
    int gw = blockIdx.x * 8 + wid;
    int* rankslot = (int*)g_cra;   // rank lives in .y of float2
    if (gw < NDIG) {
        int d = gw;
        int base = g_base[d];
        int n = g_cursor[d] - base;
        if (n == 0) return;
        if (n <= 32) {
            unsigned rec = (lane < n) ? g_bin[base + lane] : 0xFFFFFFFFu;
            int r = 0;
            for (int k = 0; k < n; k++) {
                unsigned other = __shfl_sync(FULLM, rec, k);
                r += (other < rec) ? 1 : 0;
            }
            if (lane < n) {
                int cpos = rec & 0x7FFFu;
                int rank = base + r;
                rankslot[2 * cpos + 1] = rank;
                g_ridx[rank] = g_cidx[cpos];
            }
        } else {
            for (int e = lane; e < n; e += 32) {
                unsigned rec = g_bin[base + e];
                int r = 0;
                for (int k = 0; k < n; k++) r += (g_bin[base + k] < rec) ? 1 : 0;
                int cpos = rec & 0x7FFFu;
                int rank = base + r;
                rankslot[2 * cpos + 1] = rank;
                g_ridx[rank] = g_cidx[cpos];
            }
        }
    } else {
        // tile-bbox warps over the compacted array
        int tile = gw - NDIG;
        if (tile >= NCTILE) return;
        int kcnt = g_kcnt;
        int kk = tile * 32 + lane;
        bool on = kk < kcnt;
        float x1 = 0.f, y1 = 0.f, x2 = 0.f, y2 = 0.f, area = 0.f;
        if (on) {
            float4 b = g_cbox[kk];
            x1 = b.x; y1 = b.y; x2 = b.z; y2 = b.w;
            area = box_area(x1, y1, x2, y2);
        }
        float r0 = on ? x1 :  1e30f;
        float r1 = on ? y1 :  1e30f;
        float r2 = on ? x2 : -1e30f;
        float r3 = on ? y2 : -1e30f;
        float r4 = on ? area :  1e30f;
        float r5 = on ? area : -1e30f;
        #pragma unroll
        for (int s = 16; s > 0; s >>= 1) {
            r0 = fminf(r0, __shfl_xor_sync(FULLM, r0, s));
            r1 = fminf(r1, __shfl_xor_sync(FULLM, r1, s));
            r2 = fmaxf(r2, __shfl_xor_sync(FULLM, r2, s));
            r3 = fmaxf(r3, __shfl_xor_sync(FULLM, r3, s));
            r4 = fminf(r4, __shfl_xor_sync(FULLM, r4, s));
            r5 = fmaxf(r5, __shfl_xor_sync(FULLM, r5, s));
        }
        if (lane == 0) {
            g_tbb[tile] = make_float4(r0, r1, r2, r3);
            g_tar[tile] = make_float2(r4, r5);
        }
    }
}

// ---------------- K5: sparse suppressor lists (warp per compacted box) ----------------
// candidate gate: one 8B load (area, rank); rank + area-ratio reject before 16B box load.
// IoU <= min(area)/max(area) under monotone rn rounding, so ratio <= 0.299 can never
// produce iou > 0.3 (slack 0.3/0.299 >> rounding).
__global__ void k_nbr() {
    int kq = (blockIdx.x * blockDim.x + threadIdx.x) >> 5;
    int lane = threadIdx.x & 31;
    int kcnt = g_kcnt;
    if (kq >= kcnt) return;
    float2 me = g_cra[kq];
    float ai = me.x;
    int ri = __float_as_int(me.y);
    float4 bb = g_cbox[kq];
    float x1 = bb.x, y1 = bb.y, x2 = bb.z, y2 = bb.w;
    int ntile = (kcnt + 31) >> 5;
    int cnt = 0;
    for (int tb = 0; tb < ntile; tb += 32) {
        int t = tb + lane;
        bool act = false;
        if (t < ntile) {
            float4 tbv = g_tbb[t];
            float2 tav = g_tar[t];
            float bw = __fadd_rn(__fsub_rn(fminf(x2, tbv.z), fmaxf(x1, tbv.x)), 1.0f);
            float bh = __fadd_rn(__fsub_rn(fminf(y2, tbv.w), fmaxf(y1, tbv.y)), 1.0f);
            float lo = fminf(ai, tav.y);
            float hi = fmaxf(ai, tav.x);
            act = (bw > 0.f) && (bh > 0.f) && (lo > 0.299f * hi);  // conservative
        }
        unsigned bal = __ballot_sync(FULLM, act);
        while (bal) {
            int tt = __ffs(bal) - 1;
            bal &= bal - 1;
            int j = ((tb + tt) << 5) + lane;
            bool hit = false;
            int rj = 0x7FFFFFFF;
            if (j < kcnt) {
                float2 ca = g_cra[j];
                rj = __float_as_int(ca.y);
                float aj = ca.x;
                if (rj < ri && fminf(ai, aj) > 0.299f * fmaxf(ai, aj)) {
                    float4 bj = g_cbox[j];
                    float xx1 = fmaxf(x1, bj.x);
                    float yy1 = fmaxf(y1, bj.y);
                    float xx2 = fminf(x2, bj.z);
                    float yy2 = fminf(y2, bj.w);
                    float w  = fmaxf(__fadd_rn(__fsub_rn(xx2, xx1), 1.f), 0.f);
                    float hh = fmaxf(__fadd_rn(__fsub_rn(yy2, yy1), 1.f), 0.f);
                    float inter = __fmul_rn(w, hh);
                    if (inter > 0.299f * fmaxf(ai, aj)) {
                        float iou = __fdiv_rn(inter, __fsub_rn(__fadd_rn(ai, aj), inter));
                        hit = iou > NMS_THF;
                    }
                }
            }
            unsigned hb = __ballot_sync(FULLM, hit);
            if (hit) {
                int off = cnt + __popc(hb & ((1u << lane) - 1));
                if (off < CAP) g_nbr[(size_t)ri * CAP + off] = (unsigned short)rj;
            }
            cnt += __popc(hb);
        }
    }
    if (lane == 0) g_ncnt[ri] = min(cnt, CAP);
}

// ---------------- K6: dataflow NMS resolve + output write (+ hist re-zero) ----------------
// dependency edges always point to strictly lower ranks -> DAG -> no deadlock.
__global__ void __launch_bounds__(256) k_resolve(float* __restrict__ out) {
    int gid = blockIdx.x * 256 + threadIdx.x;
    if (gid < NDIG) g_hist[gid] = 0;   // reset for next replay
    int gw = gid >> 5;
    int lane = threadIdx.x & 31;
    int kcnt = g_kcnt;
    for (int r = gw; r < kcnt; r += NRW) {
        int cn = g_ncnt[r];
        const unsigned short* lst = g_nbr + (size_t)r * CAP;
        bool removed = false;
        for (int b = 0; b < cn && !removed; b += 32) {
            int e = b + lane;
            int c = (e < cn) ? (int)lst[e] : 0;
            bool pend = (e < cn);
            bool kept = false;
            for (;;) {
                if (pend) {
                    unsigned long long w = *(volatile unsigned long long*)&g_state[c >> 5];
                    unsigned long long sv = w >> ((c & 31) * 2);
                    if (sv & 1ull) { kept = (sv & 2ull) != 0ull; pend = false; }
                }
                if (__ballot_sync(FULLM, kept)) { removed = true; break; }
                if (!__ballot_sync(FULLM, pend)) break;
                __nanosleep(32);
            }
        }
        if (lane == 0) {
            atomicOr(&g_state[r >> 5], (removed ? 1ull : 3ull) << ((r & 31) * 2));
            int idx = g_ridx[r];
            float f = removed ? 0.0f : 1.0f;
            float4 bb = g_box[idx];
            out[idx * 5 + 0] = __fmul_rn(bb.x, f);
            out[idx * 5 + 1] = __fmul_rn(bb.y, f);
            out[idx * 5 + 2] = __fmul_rn(bb.z, f);
            out[idx * 5 + 3] = __fmul_rn(bb.w, f);
            out[idx * 5 + 4] = __fmul_rn(g_sc[idx], f);
        }
    }
}

extern "C" void kernel_launch(void* const* d_in, const int* in_sizes, int n_in,
                              void* d_out, int out_size) {
    (void)in_sizes; (void)n_in; (void)out_size;
    InPtrs p;
    for (int i = 0; i < 6; i++) {
        p.cls[i] = (const float*)d_in[2 * i];
        p.reg[i] = (const float*)d_in[2 * i + 1];
    }
    float* out = (float*)d_out;
    k_decode<<<NBLK, 256>>>(p, out);
    k_scan<<<1, 1024>>>();
    k_scatter<<<NBLK, 256>>>();
    k_binsort<<<NDIG / 8 + (NCTILE + 7) / 8, 256>>>();
    k_nbr<<<(N_ANCH * 32 + 255) / 256, 256>>>();
    k_resolve<<<NRB, 256>>>(out);
}